// round 2
// baseline (speedup 1.0000x reference)
#include <cuda_runtime.h>
#include <mma.h>
#include <math.h>

using namespace nvcuda;

#define HIDDEN 3584
#define NH 28
#define NKV 4
#define HD 128
#define NREP 7
#define BATCH 2
#define SEQ 2048
#define M_TOK (BATCH*SEQ)   // 4096
#define QDIM (NH*HD)        // 3584
#define KVDIM (NKV*HD)      // 512

// ---------------------------------------------------------------------------
// Scratch (static device globals; no runtime allocation allowed)
// ---------------------------------------------------------------------------
__device__ float g_Cq[(size_t)M_TOK*QDIM];    // raw Q proj  [M, 3584]
__device__ float g_Ck[(size_t)M_TOK*KVDIM];   // raw K proj  [M, 512]
__device__ float g_Cv[(size_t)M_TOK*KVDIM];   // raw V proj  [M, 512]
__device__ float g_Q [(size_t)M_TOK*QDIM];    // [B][NH][S][D], rope'd + scaled
__device__ float g_K [(size_t)M_TOK*KVDIM];   // [B][NKV][S][D], rope'd
__device__ float g_V [(size_t)M_TOK*KVDIM];   // [B][NKV][S][D]
__device__ float g_A [(size_t)M_TOK*QDIM];    // attention out [B][S][NH*D]

// split helper: x -> (hi, lo) both representable in tf32
__device__ __forceinline__ void tf32_split(float x, float& hi, float& lo) {
    hi = wmma::__float_to_tf32(x);
    lo = wmma::__float_to_tf32(x - hi);
}

// ---------------------------------------------------------------------------
// 3xTF32 WMMA GEMM:  C[M,N] = A[M,K] @ W[N,K]^T   (fp32-accurate)
// BM=128 BN=128 BK=32, 8 warps, each warp 32x64 (2x4 m16n16k8 tiles)
// ---------------------------------------------------------------------------
#define BM 128
#define BN 128
#define BK 32

typedef wmma::fragment<wmma::matrix_a,16,16,8,wmma::precision::tf32,wmma::row_major> AFrag;
typedef wmma::fragment<wmma::matrix_b,16,16,8,wmma::precision::tf32,wmma::col_major> BFragC;
typedef wmma::fragment<wmma::matrix_b,16,16,8,wmma::precision::tf32,wmma::row_major> BFragR;
typedef wmma::fragment<wmma::accumulator,16,16,8,float> CFrag;

__global__ void __launch_bounds__(256) gemm_tf32(
    const float* __restrict__ A, const float* __restrict__ W,
    float* __restrict__ C, int M, int N, int K)
{
    __shared__ __align__(16) float As[BM][BK];
    __shared__ __align__(16) float Ws[BN][BK];
    const int bm = blockIdx.y * BM;
    const int bn = blockIdx.x * BN;
    const int tid = threadIdx.x;
    const int warp = tid >> 5;
    const int wr = warp >> 1;     // 0..3 : 32-row band
    const int wc = warp & 1;      // 0..1 : 64-col band

    CFrag acc[2][4];
    #pragma unroll
    for (int i = 0; i < 2; i++)
        #pragma unroll
        for (int j = 0; j < 4; j++)
            wmma::fill_fragment(acc[i][j], 0.0f);

    for (int k0 = 0; k0 < K; k0 += BK) {
        #pragma unroll
        for (int i = 0; i < 4; i++) {
            int idx = tid + i*256;            // float4 index, 1024 per tile
            int row = idx >> 3, c4 = idx & 7;
            *(float4*)&As[row][c4*4] =
                *(const float4*)&A[(size_t)(bm+row)*K + k0 + c4*4];
            *(float4*)&Ws[row][c4*4] =
                *(const float4*)&W[(size_t)(bn+row)*K + k0 + c4*4];
        }
        __syncthreads();
        #pragma unroll
        for (int kk = 0; kk < 4; kk++) {
            const int ks = kk*8;
            AFrag  ah[2], al[2];
            BFragC bh[4], bl[4];
            #pragma unroll
            for (int i = 0; i < 2; i++) {
                wmma::load_matrix_sync(ah[i], &As[wr*32 + i*16][ks], BK);
                #pragma unroll
                for (int t = 0; t < ah[i].num_elements; t++)
                    tf32_split(ah[i].x[t], ah[i].x[t], al[i].x[t]);
            }
            #pragma unroll
            for (int j = 0; j < 4; j++) {
                wmma::load_matrix_sync(bh[j], &Ws[wc*64 + j*16][ks], BK);
                #pragma unroll
                for (int t = 0; t < bh[j].num_elements; t++)
                    tf32_split(bh[j].x[t], bh[j].x[t], bl[j].x[t]);
            }
            #pragma unroll
            for (int i = 0; i < 2; i++)
                #pragma unroll
                for (int j = 0; j < 4; j++) {
                    wmma::mma_sync(acc[i][j], al[i], bh[j], acc[i][j]);
                    wmma::mma_sync(acc[i][j], ah[i], bl[j], acc[i][j]);
                    wmma::mma_sync(acc[i][j], ah[i], bh[j], acc[i][j]);
                }
        }
        __syncthreads();
    }

    #pragma unroll
    for (int i = 0; i < 2; i++)
        #pragma unroll
        for (int j = 0; j < 4; j++) {
            int row = bm + wr*32 + i*16;
            int col = bn + wc*64 + j*16;
            wmma::store_matrix_sync(&C[(size_t)row*N + col], acc[i][j], N,
                                    wmma::mem_row_major);
        }
}

// ---------------------------------------------------------------------------
// bias + RoPE + transpose into [B][H][S][D]; folds score scaling into Q.
// ---------------------------------------------------------------------------
__global__ void __launch_bounds__(256) pack_rope(
    const float* __restrict__ Cq, const float* __restrict__ Ck,
    const float* __restrict__ Cv,
    const float* __restrict__ bq, const float* __restrict__ bk,
    const float* __restrict__ bv,
    const float* __restrict__ cosp, const float* __restrict__ sinp)
{
    const int token = blockIdx.x;
    const int b = token / SEQ, s = token % SEQ;
    __shared__ float cs[HD], sn[HD];
    if (threadIdx.x < HD) {
        cs[threadIdx.x] = cosp[(size_t)token*HD + threadIdx.x];
        sn[threadIdx.x] = sinp[(size_t)token*HD + threadIdx.x];
    }
    __syncthreads();
    const float scaling = 0.08838834764831845f;   // 128^-0.5

    for (int i = threadIdx.x; i < NH*64; i += blockDim.x) {
        int h = i >> 6, d = i & 63;
        size_t base = (size_t)token*QDIM + h*HD;
        float x1 = Cq[base + d]      + bq[h*HD + d];
        float x2 = Cq[base + d + 64] + bq[h*HD + d + 64];
        float o1 = (x1*cs[d]      - x2*sn[d])      * scaling;
        float o2 = (x2*cs[d + 64] + x1*sn[d + 64]) * scaling;
        size_t ob = ((size_t)(b*NH + h)*SEQ + s)*HD;
        g_Q[ob + d]      = o1;
        g_Q[ob + d + 64] = o2;
    }
    for (int i = threadIdx.x; i < NKV*64; i += blockDim.x) {
        int h = i >> 6, d = i & 63;
        size_t base = (size_t)token*KVDIM + h*HD;
        float x1 = Ck[base + d]      + bk[h*HD + d];
        float x2 = Ck[base + d + 64] + bk[h*HD + d + 64];
        float o1 = x1*cs[d]      - x2*sn[d];
        float o2 = x2*cs[d + 64] + x1*sn[d + 64];
        size_t ob = ((size_t)(b*NKV + h)*SEQ + s)*HD;
        g_K[ob + d]      = o1;
        g_K[ob + d + 64] = o2;
    }
    for (int i = threadIdx.x; i < KVDIM; i += blockDim.x) {
        int h = i >> 7, d = i & 127;
        float v = Cv[(size_t)token*KVDIM + i] + bv[i];
        g_V[((size_t)(b*NKV + h)*SEQ + s)*HD + d] = v;
    }
}

// ---------------------------------------------------------------------------
// Causal GQA flash attention. BQ=BKV=64, D=128, 8 warps. 3xTF32 MMAs.
// smem: Qs 32K | Ks 32K | Vs 32K | Os 32K | Ss 16K  = 144 KB
// ---------------------------------------------------------------------------
#define BQ 64
#define BKV 64
#define ATTN_SMEM_FLOATS (8192*4 + 4096)
#define ATTN_SMEM_BYTES  (ATTN_SMEM_FLOATS*4)

__global__ void __launch_bounds__(256) attn_kernel()
{
    extern __shared__ __align__(16) float smf[];
    float* Qs = smf;                 // [64][128]
    float* Ks = smf + 8192;          // [64][128]
    float* Vs = smf + 16384;         // [64][128]
    float* Os = smf + 24576;         // [64][128]
    float* Ss = smf + 32768;         // [64][64]

    const int qt  = blockIdx.x;      // 0..31
    const int h   = blockIdx.y;      // 0..27
    const int b   = blockIdx.z;      // 0..1
    const int kvh = h / NREP;
    const int q0  = qt * BQ;
    const int tid = threadIdx.x;
    const int warp = tid >> 5;

    const float* Qg = g_Q + (size_t)(b*NH  + h  )*SEQ*HD;
    const float* Kg = g_K + (size_t)(b*NKV + kvh)*SEQ*HD;
    const float* Vg = g_V + (size_t)(b*NKV + kvh)*SEQ*HD;

    // load Q tile (pre-scaled), zero O tile
    #pragma unroll
    for (int i = 0; i < 8; i++) {
        int idx = tid + i*256;       // float4 index over 2048
        int row = idx >> 5, c4 = idx & 31;
        *(float4*)&Qs[row*HD + c4*4] =
            *(const float4*)&Qg[(size_t)(q0+row)*HD + c4*4];
        *(float4*)&Os[row*HD + c4*4] = make_float4(0.f,0.f,0.f,0.f);
    }

    const int r = tid >> 2;          // softmax row owned by this 4-group
    const int g = tid & 3;
    float m_r = -INFINITY, l_r = 0.f;

    for (int j = 0; j <= qt; j++) {
        __syncthreads();             // protect Ks/Vs/Ss/Os from prior-iter readers
        #pragma unroll
        for (int i = 0; i < 8; i++) {
            int idx = tid + i*256;
            int row = idx >> 5, c4 = idx & 31;
            *(float4*)&Ks[row*HD + c4*4] =
                *(const float4*)&Kg[(size_t)(j*BKV+row)*HD + c4*4];
            *(float4*)&Vs[row*HD + c4*4] =
                *(const float4*)&Vg[(size_t)(j*BKV+row)*HD + c4*4];
        }
        __syncthreads();

        // ---- S = Qs @ Ks^T  (64x64, k=128), 3xTF32 ----
        {
            const int wr0 = (warp >> 1) * 16;
            const int wc0 = (warp & 1) * 32;
            CFrag sc[2];
            wmma::fill_fragment(sc[0], 0.f);
            wmma::fill_fragment(sc[1], 0.f);
            #pragma unroll
            for (int ks = 0; ks < HD; ks += 8) {
                AFrag ah, al;
                wmma::load_matrix_sync(ah, &Qs[wr0*HD + ks], HD);
                #pragma unroll
                for (int t = 0; t < ah.num_elements; t++)
                    tf32_split(ah.x[t], ah.x[t], al.x[t]);
                #pragma unroll
                for (int jj = 0; jj < 2; jj++) {
                    BFragC bh, bl;
                    wmma::load_matrix_sync(bh, &Ks[(wc0 + jj*16)*HD + ks], HD);
                    #pragma unroll
                    for (int t = 0; t < bh.num_elements; t++)
                        tf32_split(bh.x[t], bh.x[t], bl.x[t]);
                    wmma::mma_sync(sc[jj], al, bh, sc[jj]);
                    wmma::mma_sync(sc[jj], ah, bl, sc[jj]);
                    wmma::mma_sync(sc[jj], ah, bh, sc[jj]);
                }
            }
            wmma::store_matrix_sync(&Ss[wr0*64 + wc0     ], sc[0], 64, wmma::mem_row_major);
            wmma::store_matrix_sync(&Ss[wr0*64 + wc0 + 16], sc[1], 64, wmma::mem_row_major);
        }
        __syncthreads();

        // ---- online softmax (4 threads per row) ----
        {
            const bool diag = (j == qt);
            float mx = -INFINITY;
            #pragma unroll
            for (int c = g; c < BKV; c += 4) {
                float v = Ss[r*64 + c];
                if (diag && (j*BKV + c > q0 + r)) v = -INFINITY;
                mx = fmaxf(mx, v);
            }
            mx = fmaxf(mx, __shfl_xor_sync(0xffffffffu, mx, 1));
            mx = fmaxf(mx, __shfl_xor_sync(0xffffffffu, mx, 2));
            float m_new = fmaxf(m_r, mx);
            float alpha = expf(m_r - m_new);
            float sum = 0.f;
            #pragma unroll
            for (int c = g; c < BKV; c += 4) {
                float v = Ss[r*64 + c];
                float p = (diag && (j*BKV + c > q0 + r)) ? 0.f : expf(v - m_new);
                Ss[r*64 + c] = p;
                sum += p;
            }
            sum += __shfl_xor_sync(0xffffffffu, sum, 1);
            sum += __shfl_xor_sync(0xffffffffu, sum, 2);
            l_r = l_r * alpha + sum;
            m_r = m_new;
            #pragma unroll
            for (int d = g; d < HD; d += 4)
                Os[r*HD + d] *= alpha;
        }
        __syncthreads();

        // ---- O += P @ V  (64x128, k=64), 3xTF32 ----
        {
            const int wr0 = (warp >> 1) * 16;
            const int wc0 = (warp & 1) * 64;
            CFrag oc[4];
            #pragma unroll
            for (int jj = 0; jj < 4; jj++)
                wmma::load_matrix_sync(oc[jj], &Os[wr0*HD + wc0 + jj*16], HD,
                                       wmma::mem_row_major);
            #pragma unroll
            for (int ks = 0; ks < BKV; ks += 8) {
                AFrag ah, al;
                wmma::load_matrix_sync(ah, &Ss[wr0*64 + ks], 64);
                #pragma unroll
                for (int t = 0; t < ah.num_elements; t++)
                    tf32_split(ah.x[t], ah.x[t], al.x[t]);
                #pragma unroll
                for (int jj = 0; jj < 4; jj++) {
                    BFragR bh, bl;
                    wmma::load_matrix_sync(bh, &Vs[ks*HD + wc0 + jj*16], HD);
                    #pragma unroll
                    for (int t = 0; t < bh.num_elements; t++)
                        tf32_split(bh.x[t], bh.x[t], bl.x[t]);
                    wmma::mma_sync(oc[jj], al, bh, oc[jj]);
                    wmma::mma_sync(oc[jj], ah, bl, oc[jj]);
                    wmma::mma_sync(oc[jj], ah, bh, oc[jj]);
                }
            }
            #pragma unroll
            for (int jj = 0; jj < 4; jj++)
                wmma::store_matrix_sync(&Os[wr0*HD + wc0 + jj*16], oc[jj], HD,
                                        wmma::mem_row_major);
        }
    }
    __syncthreads();

    // ---- epilogue: normalize + scatter to [b][s][h*d] ----
    {
        float inv = 1.f / l_r;
        float* outp = g_A + ((size_t)(b*SEQ + q0 + r))*QDIM + h*HD;
        #pragma unroll
        for (int d = g; d < HD; d += 4)
            outp[d] = Os[r*HD + d] * inv;
    }
}

// ---------------------------------------------------------------------------
// launch
// ---------------------------------------------------------------------------
extern "C" void kernel_launch(void* const* d_in, const int* in_sizes, int n_in,
                              void* d_out, int out_size)
{
    (void)in_sizes; (void)n_in; (void)out_size;
    const float* hs   = (const float*)d_in[0];
    const float* cosp = (const float*)d_in[1];
    const float* sinp = (const float*)d_in[2];
    const float* Wq   = (const float*)d_in[3];
    const float* bq   = (const float*)d_in[4];
    const float* Wk   = (const float*)d_in[5];
    const float* bk   = (const float*)d_in[6];
    const float* Wv   = (const float*)d_in[7];
    const float* bv   = (const float*)d_in[8];
    const float* Wo   = (const float*)d_in[9];
    float* out = (float*)d_out;

    float *Cq, *Ck, *Cv, *Abuf;
    cudaGetSymbolAddress((void**)&Cq,   g_Cq);
    cudaGetSymbolAddress((void**)&Ck,   g_Ck);
    cudaGetSymbolAddress((void**)&Cv,   g_Cv);
    cudaGetSymbolAddress((void**)&Abuf, g_A);

    cudaFuncSetAttribute(attn_kernel,
                         cudaFuncAttributeMaxDynamicSharedMemorySize,
                         ATTN_SMEM_BYTES);

    dim3 blk(256);
    gemm_tf32<<<dim3(QDIM/BN,  M_TOK/BM), blk>>>(hs, Wq, Cq, M_TOK, QDIM,  HIDDEN);
    gemm_tf32<<<dim3(KVDIM/BN, M_TOK/BM), blk>>>(hs, Wk, Ck, M_TOK, KVDIM, HIDDEN);
    gemm_tf32<<<dim3(KVDIM/BN, M_TOK/BM), blk>>>(hs, Wv, Cv, M_TOK, KVDIM, HIDDEN);
    pack_rope<<<M_TOK, 256>>>(Cq, Ck, Cv, bq, bk, bv, cosp, sinp);
    attn_kernel<<<dim3(SEQ/BQ, NH, BATCH), 256, ATTN_SMEM_BYTES>>>();
    gemm_tf32<<<dim3(QDIM/BN,  M_TOK/BM), blk>>>(Abuf, Wo, out, M_TOK, QDIM, HIDDEN);
}

// round 4
// speedup vs baseline: 1.9996x; 1.9996x over previous
#include <cuda_runtime.h>
#include <cuda_bf16.h>
#include <mma.h>
#include <math.h>
#include <cstdint>
#include <cstddef>

using namespace nvcuda;

#define HIDDEN 3584
#define NH 28
#define NKV 4
#define HD 128
#define NREP 7
#define BATCH 2
#define SEQ 2048
#define M_TOK (BATCH*SEQ)   // 4096
#define QDIM (NH*HD)        // 3584
#define KVDIM (NKV*HD)      // 512

typedef __nv_bfloat16 bf16;

// ---------------------------------------------------------------------------
// Scratch (static device globals; no runtime allocation allowed)
// ---------------------------------------------------------------------------
__device__ float g_Cq[(size_t)M_TOK*QDIM];    // raw Q proj
__device__ float g_Ck[(size_t)M_TOK*KVDIM];
__device__ float g_Cv[(size_t)M_TOK*KVDIM];

__device__ __align__(128) bf16 g_hsh[(size_t)M_TOK*HIDDEN];
__device__ __align__(128) bf16 g_hsl[(size_t)M_TOK*HIDDEN];
__device__ __align__(128) bf16 g_Wqh[(size_t)QDIM*HIDDEN];
__device__ __align__(128) bf16 g_Wql[(size_t)QDIM*HIDDEN];
__device__ __align__(128) bf16 g_Wkh[(size_t)KVDIM*HIDDEN];
__device__ __align__(128) bf16 g_Wkl[(size_t)KVDIM*HIDDEN];
__device__ __align__(128) bf16 g_Wvh[(size_t)KVDIM*HIDDEN];
__device__ __align__(128) bf16 g_Wvl[(size_t)KVDIM*HIDDEN];
__device__ __align__(128) bf16 g_Woh[(size_t)HIDDEN*QDIM];
__device__ __align__(128) bf16 g_Wol[(size_t)HIDDEN*QDIM];

__device__ __align__(128) bf16 g_Qh[(size_t)M_TOK*QDIM];   // [B][NH][S][D]
__device__ __align__(128) bf16 g_Ql[(size_t)M_TOK*QDIM];
__device__ __align__(128) bf16 g_Kh[(size_t)M_TOK*KVDIM];  // [B][NKV][S][D]
__device__ __align__(128) bf16 g_Kl[(size_t)M_TOK*KVDIM];
__device__ __align__(128) bf16 g_Vh[(size_t)M_TOK*KVDIM];
__device__ __align__(128) bf16 g_Vl[(size_t)M_TOK*KVDIM];
__device__ __align__(128) bf16 g_Ah[(size_t)M_TOK*QDIM];   // attn out [B][S][NH*D]
__device__ __align__(128) bf16 g_Al[(size_t)M_TOK*QDIM];

// ---------------------------------------------------------------------------
// helpers
// ---------------------------------------------------------------------------
__device__ __forceinline__ void bf16_split(float x, bf16& hi, bf16& lo) {
    hi = __float2bfloat16(x);
    lo = __float2bfloat16(x - __bfloat162float(hi));
}
__device__ __forceinline__ uint32_t smem_u32(const void* p) {
    return (uint32_t)__cvta_generic_to_shared(p);
}
__device__ __forceinline__ void cp_async16(void* s, const void* g) {
    asm volatile("cp.async.cg.shared.global [%0], [%1], 16;\n"
                 :: "r"(smem_u32(s)), "l"(g));
}

// elementwise split fp32 -> bf16 hi/lo (vectorized by 4)
__global__ void __launch_bounds__(256) split_bf16(
    const float4* __restrict__ src, __nv_bfloat162* __restrict__ hi,
    __nv_bfloat162* __restrict__ lo, size_t n4)
{
    size_t i = (size_t)blockIdx.x*blockDim.x + threadIdx.x;
    if (i >= n4) return;
    float4 v = src[i];
    bf16 hx, lx, hy, ly, hz, lz, hw, lw;
    bf16_split(v.x, hx, lx);
    bf16_split(v.y, hy, ly);
    bf16_split(v.z, hz, lz);
    bf16_split(v.w, hw, lw);
    hi[2*i]   = __nv_bfloat162(hx, hy);
    hi[2*i+1] = __nv_bfloat162(hz, hw);
    lo[2*i]   = __nv_bfloat162(lx, ly);
    lo[2*i+1] = __nv_bfloat162(lz, lw);
}

// ---------------------------------------------------------------------------
// 3xBF16 WMMA GEMM: C[M,N] = (Ah+Al)[M,K] @ (Wh+Wl)[N,K]^T  (fp32 accurate)
// BM=BN=128, BK=32; cp.async 2-stage pipeline; 8 warps, warp tile 32x64.
// ---------------------------------------------------------------------------
#define GBM 128
#define GBN 128
#define GBK 32
#define LDT 40                         // padded smem row stride (halfs)
#define GEMM_STAGE_HALFS (4*128*LDT)   // Ah,Al,Wh,Wl tiles
#define GEMM_SMEM_BYTES  (2*GEMM_STAGE_HALFS*2)

typedef wmma::fragment<wmma::matrix_a,16,16,16,bf16,wmma::row_major> AF;
typedef wmma::fragment<wmma::matrix_b,16,16,16,bf16,wmma::col_major> BFc;
typedef wmma::fragment<wmma::matrix_b,16,16,16,bf16,wmma::row_major> BFr;
typedef wmma::fragment<wmma::accumulator,16,16,16,float> CF;

__global__ void __launch_bounds__(256,2) gemm_bf16x3(
    const bf16* __restrict__ Ah, const bf16* __restrict__ Al,
    const bf16* __restrict__ Wh, const bf16* __restrict__ Wl,
    float* __restrict__ C, int M, int N, int K)
{
    extern __shared__ __align__(16) bf16 sm[];
    const int tid  = threadIdx.x;
    const int bm   = blockIdx.y * GBM;
    const int bn   = blockIdx.x * GBN;
    const int warp = tid >> 5;
    const int wr   = warp >> 1;        // 4 bands of 32 rows
    const int wc   = warp & 1;         // 2 bands of 64 cols

    CF acc[2][4];
    #pragma unroll
    for (int i = 0; i < 2; i++)
        #pragma unroll
        for (int j = 0; j < 4; j++)
            wmma::fill_fragment(acc[i][j], 0.0f);

    const bf16* srcs[4] = {Ah, Al, Wh, Wl};

    auto load_stage = [&](int stage, int k0) {
        bf16* base = sm + stage*GEMM_STAGE_HALFS;
        #pragma unroll
        for (int i = 0; i < 8; i++) {
            int c   = tid + i*256;     // 0..2047
            int t   = c >> 9;          // tile id 0..3
            int idx = c & 511;
            int row = idx >> 2, cc = idx & 3;
            int grow = (t < 2) ? (bm + row) : (bn + row);
            const bf16* g = srcs[t] + (size_t)grow*K + k0 + cc*8;
            bf16* s = base + t*(128*LDT) + row*LDT + cc*8;
            cp_async16(s, g);
        }
        asm volatile("cp.async.commit_group;\n");
    };

    const int T = K / GBK;
    load_stage(0, 0);
    for (int t = 0; t < T; t++) {
        int s = t & 1;
        if (t + 1 < T) {
            load_stage(s ^ 1, (t+1)*GBK);
            asm volatile("cp.async.wait_group 1;\n");
        } else {
            asm volatile("cp.async.wait_group 0;\n");
        }
        __syncthreads();

        const bf16* Ash = sm + s*GEMM_STAGE_HALFS;
        const bf16* Asl = Ash + 128*LDT;
        const bf16* Wsh = Asl + 128*LDT;
        const bf16* Wsl = Wsh + 128*LDT;

        #pragma unroll
        for (int ks = 0; ks < 2; ks++) {
            const int kofs = ks*16;
            AF ah[2], al[2];
            #pragma unroll
            for (int i = 0; i < 2; i++) {
                wmma::load_matrix_sync(ah[i], Ash + (wr*32 + i*16)*LDT + kofs, LDT);
                wmma::load_matrix_sync(al[i], Asl + (wr*32 + i*16)*LDT + kofs, LDT);
            }
            #pragma unroll
            for (int jj = 0; jj < 4; jj++) {
                BFc bh, bl;
                wmma::load_matrix_sync(bh, Wsh + (wc*64 + jj*16)*LDT + kofs, LDT);
                wmma::load_matrix_sync(bl, Wsl + (wc*64 + jj*16)*LDT + kofs, LDT);
                #pragma unroll
                for (int i = 0; i < 2; i++) {
                    wmma::mma_sync(acc[i][jj], al[i], bh, acc[i][jj]);
                    wmma::mma_sync(acc[i][jj], ah[i], bl, acc[i][jj]);
                    wmma::mma_sync(acc[i][jj], ah[i], bh, acc[i][jj]);
                }
            }
        }
        __syncthreads();
    }

    #pragma unroll
    for (int i = 0; i < 2; i++)
        #pragma unroll
        for (int j = 0; j < 4; j++) {
            int row = bm + wr*32 + i*16;
            int col = bn + wc*64 + j*16;
            wmma::store_matrix_sync(&C[(size_t)row*N + col], acc[i][j], N,
                                    wmma::mem_row_major);
        }
}

// ---------------------------------------------------------------------------
// bias + RoPE + transpose into [B][H][S][D] bf16 hi/lo; folds scaling into Q.
// ---------------------------------------------------------------------------
__global__ void __launch_bounds__(256) pack_rope(
    const float* __restrict__ Cq, const float* __restrict__ Ck,
    const float* __restrict__ Cv,
    const float* __restrict__ bq, const float* __restrict__ bk,
    const float* __restrict__ bv,
    const float* __restrict__ cosp, const float* __restrict__ sinp)
{
    const int token = blockIdx.x;
    const int b = token / SEQ, s = token % SEQ;
    __shared__ float cs[HD], sn[HD];
    if (threadIdx.x < HD) {
        cs[threadIdx.x] = cosp[(size_t)token*HD + threadIdx.x];
        sn[threadIdx.x] = sinp[(size_t)token*HD + threadIdx.x];
    }
    __syncthreads();
    const float scaling = 0.08838834764831845f;   // 128^-0.5

    for (int i = threadIdx.x; i < NH*64; i += blockDim.x) {
        int h = i >> 6, d = i & 63;
        size_t base = (size_t)token*QDIM + h*HD;
        float x1 = Cq[base + d]      + bq[h*HD + d];
        float x2 = Cq[base + d + 64] + bq[h*HD + d + 64];
        float o1 = (x1*cs[d]      - x2*sn[d])      * scaling;
        float o2 = (x2*cs[d + 64] + x1*sn[d + 64]) * scaling;
        size_t ob = ((size_t)(b*NH + h)*SEQ + s)*HD;
        bf16 h1, l1, h2, l2;
        bf16_split(o1, h1, l1);
        bf16_split(o2, h2, l2);
        g_Qh[ob + d] = h1;      g_Ql[ob + d] = l1;
        g_Qh[ob + d + 64] = h2; g_Ql[ob + d + 64] = l2;
    }
    for (int i = threadIdx.x; i < NKV*64; i += blockDim.x) {
        int h = i >> 6, d = i & 63;
        size_t base = (size_t)token*KVDIM + h*HD;
        float x1 = Ck[base + d]      + bk[h*HD + d];
        float x2 = Ck[base + d + 64] + bk[h*HD + d + 64];
        float o1 = x1*cs[d]      - x2*sn[d];
        float o2 = x2*cs[d + 64] + x1*sn[d + 64];
        size_t ob = ((size_t)(b*NKV + h)*SEQ + s)*HD;
        bf16 h1, l1, h2, l2;
        bf16_split(o1, h1, l1);
        bf16_split(o2, h2, l2);
        g_Kh[ob + d] = h1;      g_Kl[ob + d] = l1;
        g_Kh[ob + d + 64] = h2; g_Kl[ob + d + 64] = l2;
    }
    for (int i = threadIdx.x; i < KVDIM; i += blockDim.x) {
        int h = i >> 7, d = i & 127;
        float v = Cv[(size_t)token*KVDIM + i] + bv[i];
        size_t ob = ((size_t)(b*NKV + h)*SEQ + s)*HD + d;
        bf16 hv, lv;
        bf16_split(v, hv, lv);
        g_Vh[ob] = hv; g_Vl[ob] = lv;
    }
}

// ---------------------------------------------------------------------------
// Causal GQA flash attention, 3xBF16. BQ=BKV=64, D=128, 8 warps.
// ---------------------------------------------------------------------------
#define BQ 64
#define BKV 64
#define LDA 136   // smem stride for 128-wide bf16 tiles
#define LDP 72    // smem stride for 64-wide P tiles

// halfs: Qh,Ql,Kh,Kl,Vh,Vl each 64*136
#define AT_QH  0
#define AT_QL  (64*LDA)
#define AT_KH  (2*64*LDA)
#define AT_KL  (3*64*LDA)
#define AT_VH  (4*64*LDA)
#define AT_VL  (5*64*LDA)
#define AT_PH  (6*64*LDA)
#define AT_PL  (6*64*LDA + 64*LDP)
#define AT_HALFS (6*64*LDA + 2*64*LDP)
// floats after the halfs region (aligned: AT_HALFS*2 bytes, AT_HALFS even)
#define AT_OS  0
#define AT_SS  (64*HD)
#define AT_FLOATS (64*HD + 64*64)
#define ATTN_SMEM_BYTES (AT_HALFS*2 + AT_FLOATS*4)

__global__ void __launch_bounds__(256) attn_kernel()
{
    extern __shared__ __align__(16) char smraw[];
    bf16*  smh = (bf16*)smraw;
    float* smf = (float*)(smraw + AT_HALFS*2);
    bf16 *Qh = smh + AT_QH, *Ql = smh + AT_QL;
    bf16 *Kh = smh + AT_KH, *Kl = smh + AT_KL;
    bf16 *Vh = smh + AT_VH, *Vl = smh + AT_VL;
    bf16 *Ph = smh + AT_PH, *Pl = smh + AT_PL;
    float *Os = smf + AT_OS, *Ss = smf + AT_SS;

    const int qt  = blockIdx.x;
    const int h   = blockIdx.y;
    const int b   = blockIdx.z;
    const int kvh = h / NREP;
    const int q0  = qt * BQ;
    const int tid = threadIdx.x;
    const int warp = tid >> 5;

    const bf16* Qgh = g_Qh + (size_t)(b*NH  + h  )*SEQ*HD;
    const bf16* Qgl = g_Ql + (size_t)(b*NH  + h  )*SEQ*HD;
    const bf16* Kgh = g_Kh + (size_t)(b*NKV + kvh)*SEQ*HD;
    const bf16* Kgl = g_Kl + (size_t)(b*NKV + kvh)*SEQ*HD;
    const bf16* Vgh = g_Vh + (size_t)(b*NKV + kvh)*SEQ*HD;
    const bf16* Vgl = g_Vl + (size_t)(b*NKV + kvh)*SEQ*HD;

    // load Q tiles (hi/lo), zero O tile
    #pragma unroll
    for (int i = 0; i < 8; i++) {
        int c = tid + i*256;          // 2048 chunks: 2 tiles x 1024
        int t = c >> 10, idx = c & 1023;
        int row = idx >> 4, cc = idx & 15;
        const bf16* src = (t == 0 ? Qgh : Qgl) + (size_t)(q0+row)*HD + cc*8;
        bf16* dst = (t == 0 ? Qh : Ql) + row*LDA + cc*8;
        *(uint4*)dst = *(const uint4*)src;
    }
    #pragma unroll
    for (int i = 0; i < 8; i++) {
        int idx = tid + i*256;        // 2048 float4 over Os
        int row = idx >> 5, c4 = idx & 31;
        *(float4*)&Os[row*HD + c4*4] = make_float4(0.f,0.f,0.f,0.f);
    }

    const int r = tid >> 2;
    const int g = tid & 3;
    float m_r = -INFINITY, l_r = 0.f;

    for (int j = 0; j <= qt; j++) {
        __syncthreads();
        #pragma unroll
        for (int i = 0; i < 16; i++) {
            int c = tid + i*256;      // 4096 chunks: 4 tiles x 1024
            int t = c >> 10, idx = c & 1023;
            int row = idx >> 4, cc = idx & 15;
            const bf16* src;
            bf16* dst;
            if      (t == 0) { src = Kgh; dst = Kh; }
            else if (t == 1) { src = Kgl; dst = Kl; }
            else if (t == 2) { src = Vgh; dst = Vh; }
            else             { src = Vgl; dst = Vl; }
            *(uint4*)(dst + row*LDA + cc*8) =
                *(const uint4*)(src + (size_t)(j*BKV+row)*HD + cc*8);
        }
        __syncthreads();

        // ---- S = Q @ K^T (64x64, k=128), 3xBF16 ----
        {
            const int wr0 = (warp >> 1) * 16;
            const int wc0 = (warp & 1) * 32;
            CF sc[2];
            wmma::fill_fragment(sc[0], 0.f);
            wmma::fill_fragment(sc[1], 0.f);
            #pragma unroll
            for (int ks = 0; ks < HD; ks += 16) {
                AF ah, al;
                wmma::load_matrix_sync(ah, Qh + wr0*LDA + ks, LDA);
                wmma::load_matrix_sync(al, Ql + wr0*LDA + ks, LDA);
                #pragma unroll
                for (int jj = 0; jj < 2; jj++) {
                    BFc bh, bl;
                    wmma::load_matrix_sync(bh, Kh + (wc0 + jj*16)*LDA + ks, LDA);
                    wmma::load_matrix_sync(bl, Kl + (wc0 + jj*16)*LDA + ks, LDA);
                    wmma::mma_sync(sc[jj], al, bh, sc[jj]);
                    wmma::mma_sync(sc[jj], ah, bl, sc[jj]);
                    wmma::mma_sync(sc[jj], ah, bh, sc[jj]);
                }
            }
            wmma::store_matrix_sync(&Ss[wr0*64 + wc0     ], sc[0], 64, wmma::mem_row_major);
            wmma::store_matrix_sync(&Ss[wr0*64 + wc0 + 16], sc[1], 64, wmma::mem_row_major);
        }
        __syncthreads();

        // ---- online softmax (4 threads per row); write P hi/lo ----
        {
            const bool diag = (j == qt);
            float mx = -INFINITY;
            #pragma unroll
            for (int c = g; c < BKV; c += 4) {
                float v = Ss[r*64 + c];
                if (diag && (j*BKV + c > q0 + r)) v = -INFINITY;
                mx = fmaxf(mx, v);
            }
            mx = fmaxf(mx, __shfl_xor_sync(0xffffffffu, mx, 1));
            mx = fmaxf(mx, __shfl_xor_sync(0xffffffffu, mx, 2));
            float m_new = fmaxf(m_r, mx);
            float alpha = expf(m_r - m_new);
            float sum = 0.f;
            #pragma unroll
            for (int c = g; c < BKV; c += 4) {
                float v = Ss[r*64 + c];
                float p = (diag && (j*BKV + c > q0 + r)) ? 0.f : expf(v - m_new);
                bf16 ph, pl;
                bf16_split(p, ph, pl);
                Ph[r*LDP + c] = ph;
                Pl[r*LDP + c] = pl;
                sum += p;
            }
            sum += __shfl_xor_sync(0xffffffffu, sum, 1);
            sum += __shfl_xor_sync(0xffffffffu, sum, 2);
            l_r = l_r * alpha + sum;
            m_r = m_new;
            #pragma unroll
            for (int d = g; d < HD; d += 4)
                Os[r*HD + d] *= alpha;
        }
        __syncthreads();

        // ---- O += P @ V (64x128, k=64), 3xBF16 ----
        {
            const int wr0 = (warp >> 1) * 16;
            const int wc0 = (warp & 1) * 64;
            CF oc[4];
            #pragma unroll
            for (int jj = 0; jj < 4; jj++)
                wmma::load_matrix_sync(oc[jj], &Os[wr0*HD + wc0 + jj*16], HD,
                                       wmma::mem_row_major);
            #pragma unroll
            for (int ks = 0; ks < BKV; ks += 16) {
                AF ah, al;
                wmma::load_matrix_sync(ah, Ph + wr0*LDP + ks, LDP);
                wmma::load_matrix_sync(al, Pl + wr0*LDP + ks, LDP);
                #pragma unroll
                for (int jj = 0; jj < 4; jj++) {
                    BFr bh, bl;
                    wmma::load_matrix_sync(bh, Vh + ks*LDA + wc0 + jj*16, LDA);
                    wmma::load_matrix_sync(bl, Vl + ks*LDA + wc0 + jj*16, LDA);
                    wmma::mma_sync(oc[jj], al, bh, oc[jj]);
                    wmma::mma_sync(oc[jj], ah, bl, oc[jj]);
                    wmma::mma_sync(oc[jj], ah, bh, oc[jj]);
                }
            }
            #pragma unroll
            for (int jj = 0; jj < 4; jj++)
                wmma::store_matrix_sync(&Os[wr0*HD + wc0 + jj*16], oc[jj], HD,
                                        wmma::mem_row_major);
        }
    }
    __syncthreads();

    // ---- epilogue: normalize + split + scatter to [b][s][h*d] ----
    {
        float inv = 1.f / l_r;
        size_t ob = ((size_t)(b*SEQ + q0 + r))*QDIM + h*HD;
        #pragma unroll
        for (int d = g; d < HD; d += 4) {
            float v = Os[r*HD + d] * inv;
            bf16 hv, lv;
            bf16_split(v, hv, lv);
            g_Ah[ob + d] = hv;
            g_Al[ob + d] = lv;
        }
    }
}

// ---------------------------------------------------------------------------
// launch
// ---------------------------------------------------------------------------
extern "C" void kernel_launch(void* const* d_in, const int* in_sizes, int n_in,
                              void* d_out, int out_size)
{
    (void)in_sizes; (void)n_in; (void)out_size;
    const float* hs   = (const float*)d_in[0];
    const float* cosp = (const float*)d_in[1];
    const float* sinp = (const float*)d_in[2];
    const float* Wq   = (const float*)d_in[3];
    const float* bq   = (const float*)d_in[4];
    const float* Wk   = (const float*)d_in[5];
    const float* bk   = (const float*)d_in[6];
    const float* Wv   = (const float*)d_in[7];
    const float* bv   = (const float*)d_in[8];
    const float* Wo   = (const float*)d_in[9];
    float* out = (float*)d_out;

    float *Cq, *Ck, *Cv;
    bf16 *hsh, *hsl, *Wqh, *Wql, *Wkh, *Wkl, *Wvh, *Wvl, *Woh, *Wol;
    bf16 *Ah, *Al;
    cudaGetSymbolAddress((void**)&Cq,  g_Cq);
    cudaGetSymbolAddress((void**)&Ck,  g_Ck);
    cudaGetSymbolAddress((void**)&Cv,  g_Cv);
    cudaGetSymbolAddress((void**)&hsh, g_hsh);
    cudaGetSymbolAddress((void**)&hsl, g_hsl);
    cudaGetSymbolAddress((void**)&Wqh, g_Wqh);
    cudaGetSymbolAddress((void**)&Wql, g_Wql);
    cudaGetSymbolAddress((void**)&Wkh, g_Wkh);
    cudaGetSymbolAddress((void**)&Wkl, g_Wkl);
    cudaGetSymbolAddress((void**)&Wvh, g_Wvh);
    cudaGetSymbolAddress((void**)&Wvl, g_Wvl);
    cudaGetSymbolAddress((void**)&Woh, g_Woh);
    cudaGetSymbolAddress((void**)&Wol, g_Wol);
    cudaGetSymbolAddress((void**)&Ah,  g_Ah);
    cudaGetSymbolAddress((void**)&Al,  g_Al);

    cudaFuncSetAttribute(gemm_bf16x3,
                         cudaFuncAttributeMaxDynamicSharedMemorySize,
                         GEMM_SMEM_BYTES);
    cudaFuncSetAttribute(attn_kernel,
                         cudaFuncAttributeMaxDynamicSharedMemorySize,
                         ATTN_SMEM_BYTES);

    auto split = [&](const float* src, bf16* hi, bf16* lo, size_t n) {
        size_t n4 = n / 4;
        split_bf16<<<(unsigned)((n4 + 255)/256), 256>>>(
            (const float4*)src, (__nv_bfloat162*)hi, (__nv_bfloat162*)lo, n4);
    };
    split(hs, hsh, hsl, (size_t)M_TOK*HIDDEN);
    split(Wq, Wqh, Wql, (size_t)QDIM*HIDDEN);
    split(Wk, Wkh, Wkl, (size_t)KVDIM*HIDDEN);
    split(Wv, Wvh, Wvl, (size_t)KVDIM*HIDDEN);
    split(Wo, Woh, Wol, (size_t)HIDDEN*QDIM);

    dim3 blk(256);
    gemm_bf16x3<<<dim3(QDIM/GBN,  M_TOK/GBM), blk, GEMM_SMEM_BYTES>>>(
        hsh, hsl, Wqh, Wql, Cq, M_TOK, QDIM,  HIDDEN);
    gemm_bf16x3<<<dim3(KVDIM/GBN, M_TOK/GBM), blk, GEMM_SMEM_BYTES>>>(
        hsh, hsl, Wkh, Wkl, Ck, M_TOK, KVDIM, HIDDEN);
    gemm_bf16x3<<<dim3(KVDIM/GBN, M_TOK/GBM), blk, GEMM_SMEM_BYTES>>>(
        hsh, hsl, Wvh, Wvl, Cv, M_TOK, KVDIM, HIDDEN);
    pack_rope<<<M_TOK, 256>>>(Cq, Ck, Cv, bq, bk, bv, cosp, sinp);
    attn_kernel<<<dim3(SEQ/BQ, NH, BATCH), 256, ATTN_SMEM_BYTES>>>();
    gemm_bf16x3<<<dim3(QDIM/GBN,  M_TOK/GBM), blk, GEMM_SMEM_BYTES>>>(
        Ah, Al, Woh, Wol, out, M_TOK, QDIM, HIDDEN);
}

// round 6
// speedup vs baseline: 2.9250x; 1.4628x over previous
#include <cuda_runtime.h>
#include <cuda_bf16.h>
#include <mma.h>
#include <math.h>
#include <cstdint>
#include <cstddef>

using namespace nvcuda;

#define HIDDEN 3584
#define NH 28
#define NKV 4
#define HD 128
#define NREP 7
#define BATCH 2
#define SEQ 2048
#define M_TOK (BATCH*SEQ)   // 4096
#define QDIM (NH*HD)        // 3584
#define KVDIM (NKV*HD)      // 512
#define NDIMC (QDIM + 2*KVDIM)   // 4608 combined QKV output dim

typedef __nv_bfloat16 bf16;

// ---------------------------------------------------------------------------
// Scratch (static device globals; no runtime allocation allowed)
// ---------------------------------------------------------------------------
__device__ float g_Cqkv[(size_t)M_TOK*NDIMC];   // combined QKV projection

__device__ __align__(128) bf16 g_hsh[(size_t)M_TOK*HIDDEN];
__device__ __align__(128) bf16 g_hsl[(size_t)M_TOK*HIDDEN];
__device__ __align__(128) bf16 g_Wch[(size_t)NDIMC*HIDDEN];   // Wq|Wk|Wv rows
__device__ __align__(128) bf16 g_Wcl[(size_t)NDIMC*HIDDEN];
__device__ __align__(128) bf16 g_Woh[(size_t)HIDDEN*QDIM];
__device__ __align__(128) bf16 g_Wol[(size_t)HIDDEN*QDIM];

__device__ __align__(128) bf16 g_Qh[(size_t)M_TOK*QDIM];   // [B][NH][S][D]
__device__ __align__(128) bf16 g_Ql[(size_t)M_TOK*QDIM];
__device__ __align__(128) bf16 g_Kh[(size_t)M_TOK*KVDIM];  // [B][NKV][S][D]
__device__ __align__(128) bf16 g_Kl[(size_t)M_TOK*KVDIM];
__device__ __align__(128) bf16 g_Vh[(size_t)M_TOK*KVDIM];
__device__ __align__(128) bf16 g_Vl[(size_t)M_TOK*KVDIM];
__device__ __align__(128) bf16 g_Ah[(size_t)M_TOK*QDIM];   // attn out [B][S][NH*D]
__device__ __align__(128) bf16 g_Al[(size_t)M_TOK*QDIM];

// ---------------------------------------------------------------------------
// helpers
// ---------------------------------------------------------------------------
__device__ __forceinline__ void bf16_split(float x, bf16& hi, bf16& lo) {
    hi = __float2bfloat16(x);
    lo = __float2bfloat16(x - __bfloat162float(hi));
}
__device__ __forceinline__ uint32_t smem_u32(const void* p) {
    return (uint32_t)__cvta_generic_to_shared(p);
}
__device__ __forceinline__ void cp_async16_sm(uint32_t s, const void* g) {
    asm volatile("cp.async.cg.shared.global [%0], [%1], 16;\n"
                 :: "r"(s), "l"(g));
}

// elementwise split fp32 -> bf16 hi/lo (vectorized by 4)
__global__ void __launch_bounds__(256) split_bf16(
    const float4* __restrict__ src, __nv_bfloat162* __restrict__ hi,
    __nv_bfloat162* __restrict__ lo, size_t n4)
{
    size_t i = (size_t)blockIdx.x*blockDim.x + threadIdx.x;
    if (i >= n4) return;
    float4 v = src[i];
    bf16 hx, lx, hy, ly, hz, lz, hw, lw;
    bf16_split(v.x, hx, lx);
    bf16_split(v.y, hy, ly);
    bf16_split(v.z, hz, lz);
    bf16_split(v.w, hw, lw);
    hi[2*i]   = __nv_bfloat162(hx, hy);
    hi[2*i+1] = __nv_bfloat162(hz, hw);
    lo[2*i]   = __nv_bfloat162(lx, ly);
    lo[2*i+1] = __nv_bfloat162(lz, lw);
}

// ---------------------------------------------------------------------------
// 3xBF16 WMMA GEMM v2: C[M,N] = (Ah+Al)[M,K] @ (Wh+Wl)[N,K]^T
// BM=256 BN=128 BK=32, 3-stage cp.async, 1 sync/chunk, 16 warps (64x32 tiles)
// ---------------------------------------------------------------------------
#define BM2 256
#define BN2 128
#define BK2 32
#define LDT2 40                              // padded smem row stride (halfs)
#define OFF_AH 0
#define OFF_AL (BM2*LDT2)
#define OFF_BH (2*BM2*LDT2)
#define OFF_BL (2*BM2*LDT2 + BN2*LDT2)
#define STAGE2_HALFS (2*BM2*LDT2 + 2*BN2*LDT2)   // 30720
#define NSTAGE2 3
#define SMEM2_BYTES (NSTAGE2*STAGE2_HALFS*2)     // 184320

typedef wmma::fragment<wmma::matrix_a,16,16,16,bf16,wmma::row_major> AF;
typedef wmma::fragment<wmma::matrix_b,16,16,16,bf16,wmma::col_major> BFc;
typedef wmma::fragment<wmma::matrix_b,16,16,16,bf16,wmma::row_major> BFr;
typedef wmma::fragment<wmma::accumulator,16,16,16,float> CF;

__global__ void __launch_bounds__(512) gemm_v2(
    const bf16* __restrict__ Ah, const bf16* __restrict__ Al,
    const bf16* __restrict__ Wh, const bf16* __restrict__ Wl,
    float* __restrict__ C, int M, int N, int K)
{
    extern __shared__ __align__(16) bf16 sm[];
    const uint32_t smb = smem_u32(sm);
    const int tid  = threadIdx.x;
    const int warp = tid >> 5;
    const int wr   = warp >> 2;        // 0..3 : 64-row band
    const int wc   = warp & 3;         // 0..3 : 32-col band
    const int bm   = blockIdx.y * BM2;
    const int bn   = blockIdx.x * BN2;

    CF acc[4][2];
    #pragma unroll
    for (int i = 0; i < 4; i++)
        #pragma unroll
        for (int j = 0; j < 2; j++)
            wmma::fill_fragment(acc[i][j], 0.0f);

    auto load_chunk = [&](int chunk, int slot) {
        const int k0 = chunk * BK2;
        const uint32_t base = smb + (uint32_t)(slot*STAGE2_HALFS*2);
        #pragma unroll
        for (int it = 0; it < 6; it++) {
            int c = tid + it*512;              // 0..3071 16B transfers
            const bf16* g;
            uint32_t soff;
            if (c < 2048) {                    // A hi/lo: 2 x 1024
                int t = c >> 10, idx = c & 1023;
                int row = idx >> 2, c16 = idx & 3;
                g = (t ? Al : Ah) + (size_t)(bm+row)*K + k0 + c16*8;
                soff = (uint32_t)(((t ? OFF_AL : OFF_AH) + row*LDT2 + c16*8) * 2);
            } else {                           // B hi/lo: 2 x 512
                int d = c - 2048;
                int t = d >> 9, idx = d & 511;
                int row = idx >> 2, c16 = idx & 3;
                g = (t ? Wl : Wh) + (size_t)(bn+row)*K + k0 + c16*8;
                soff = (uint32_t)(((t ? OFF_BL : OFF_BH) + row*LDT2 + c16*8) * 2);
            }
            cp_async16_sm(base + soff, g);
        }
        asm volatile("cp.async.commit_group;" ::: "memory");
    };

    const int T = K / BK2;
    load_chunk(0, 0);
    load_chunk(1, 1);

    for (int i = 0; i < T; i++) {
        const int slot = i % NSTAGE2;
        if (i + 1 < T) asm volatile("cp.async.wait_group 1;" ::: "memory");
        else           asm volatile("cp.async.wait_group 0;" ::: "memory");
        __syncthreads();
        if (i + 2 < T) load_chunk(i + 2, (i + 2) % NSTAGE2);

        const bf16* st = sm + slot*STAGE2_HALFS;
        #pragma unroll
        for (int ks = 0; ks < 2; ks++) {
            const int kofs = ks*16;
            AF ah[4], al[4];
            #pragma unroll
            for (int i4 = 0; i4 < 4; i4++) {
                wmma::load_matrix_sync(ah[i4], st + OFF_AH + (wr*64 + i4*16)*LDT2 + kofs, LDT2);
                wmma::load_matrix_sync(al[i4], st + OFF_AL + (wr*64 + i4*16)*LDT2 + kofs, LDT2);
            }
            #pragma unroll
            for (int jj = 0; jj < 2; jj++) {
                BFc bh, bl;
                wmma::load_matrix_sync(bh, st + OFF_BH + (wc*32 + jj*16)*LDT2 + kofs, LDT2);
                wmma::load_matrix_sync(bl, st + OFF_BL + (wc*32 + jj*16)*LDT2 + kofs, LDT2);
                #pragma unroll
                for (int i4 = 0; i4 < 4; i4++) {
                    wmma::mma_sync(acc[i4][jj], al[i4], bh, acc[i4][jj]);
                    wmma::mma_sync(acc[i4][jj], ah[i4], bl, acc[i4][jj]);
                    wmma::mma_sync(acc[i4][jj], ah[i4], bh, acc[i4][jj]);
                }
            }
        }
    }

    #pragma unroll
    for (int i4 = 0; i4 < 4; i4++)
        #pragma unroll
        for (int jj = 0; jj < 2; jj++) {
            int row = bm + wr*64 + i4*16;
            int col = bn + wc*32 + jj*16;
            wmma::store_matrix_sync(&C[(size_t)row*N + col], acc[i4][jj], N,
                                    wmma::mem_row_major);
        }
}

// ---------------------------------------------------------------------------
// bias + RoPE + transpose into [B][H][S][D] bf16 hi/lo; folds scaling into Q.
// Reads the combined [M, 4608] projection buffer.
// ---------------------------------------------------------------------------
__global__ void __launch_bounds__(256) pack_rope(
    const float* __restrict__ Cqkv,
    const float* __restrict__ bq, const float* __restrict__ bk,
    const float* __restrict__ bv,
    const float* __restrict__ cosp, const float* __restrict__ sinp)
{
    const int token = blockIdx.x;
    const int b = token / SEQ, s = token % SEQ;
    __shared__ float cs[HD], sn[HD];
    if (threadIdx.x < HD) {
        cs[threadIdx.x] = cosp[(size_t)token*HD + threadIdx.x];
        sn[threadIdx.x] = sinp[(size_t)token*HD + threadIdx.x];
    }
    __syncthreads();
    const float scaling = 0.08838834764831845f;   // 128^-0.5
    const float* Crow = Cqkv + (size_t)token*NDIMC;

    for (int i = threadIdx.x; i < NH*64; i += blockDim.x) {
        int h = i >> 6, d = i & 63;
        float x1 = Crow[h*HD + d]      + bq[h*HD + d];
        float x2 = Crow[h*HD + d + 64] + bq[h*HD + d + 64];
        float o1 = (x1*cs[d]      - x2*sn[d])      * scaling;
        float o2 = (x2*cs[d + 64] + x1*sn[d + 64]) * scaling;
        size_t ob = ((size_t)(b*NH + h)*SEQ + s)*HD;
        bf16 h1, l1, h2, l2;
        bf16_split(o1, h1, l1);
        bf16_split(o2, h2, l2);
        g_Qh[ob + d] = h1;      g_Ql[ob + d] = l1;
        g_Qh[ob + d + 64] = h2; g_Ql[ob + d + 64] = l2;
    }
    for (int i = threadIdx.x; i < NKV*64; i += blockDim.x) {
        int h = i >> 6, d = i & 63;
        float x1 = Crow[QDIM + h*HD + d]      + bk[h*HD + d];
        float x2 = Crow[QDIM + h*HD + d + 64] + bk[h*HD + d + 64];
        float o1 = x1*cs[d]      - x2*sn[d];
        float o2 = x2*cs[d + 64] + x1*sn[d + 64];
        size_t ob = ((size_t)(b*NKV + h)*SEQ + s)*HD;
        bf16 h1, l1, h2, l2;
        bf16_split(o1, h1, l1);
        bf16_split(o2, h2, l2);
        g_Kh[ob + d] = h1;      g_Kl[ob + d] = l1;
        g_Kh[ob + d + 64] = h2; g_Kl[ob + d + 64] = l2;
    }
    for (int i = threadIdx.x; i < KVDIM; i += blockDim.x) {
        int h = i >> 7, d = i & 127;
        float v = Crow[QDIM + KVDIM + i] + bv[i];
        size_t ob = ((size_t)(b*NKV + h)*SEQ + s)*HD + d;
        bf16 hv, lv;
        bf16_split(v, hv, lv);
        g_Vh[ob] = hv; g_Vl[ob] = lv;
    }
}

// ---------------------------------------------------------------------------
// Causal GQA flash attention, 3xBF16 WMMA. BQ=BKV=64, D=128, 8 warps.
// ---------------------------------------------------------------------------
#define BQ 64
#define BKV 64
#define LDA 136
#define LDP 72

#define AT_QH  0
#define AT_QL  (64*LDA)
#define AT_KH  (2*64*LDA)
#define AT_KL  (3*64*LDA)
#define AT_VH  (4*64*LDA)
#define AT_VL  (5*64*LDA)
#define AT_PH  (6*64*LDA)
#define AT_PL  (6*64*LDA + 64*LDP)
#define AT_HALFS (6*64*LDA + 2*64*LDP)
#define AT_OS  0
#define AT_SS  (64*HD)
#define AT_FLOATS (64*HD + 64*64)
#define ATTN_SMEM_BYTES (AT_HALFS*2 + AT_FLOATS*4)

__global__ void __launch_bounds__(256) attn_kernel()
{
    extern __shared__ __align__(16) char smraw[];
    bf16*  smh = (bf16*)smraw;
    float* smf = (float*)(smraw + AT_HALFS*2);
    bf16 *Qh = smh + AT_QH, *Ql = smh + AT_QL;
    bf16 *Kh = smh + AT_KH, *Kl = smh + AT_KL;
    bf16 *Vh = smh + AT_VH, *Vl = smh + AT_VL;
    bf16 *Ph = smh + AT_PH, *Pl = smh + AT_PL;
    float *Os = smf + AT_OS, *Ss = smf + AT_SS;

    const int qt  = blockIdx.x;
    const int h   = blockIdx.y;
    const int b   = blockIdx.z;
    const int kvh = h / NREP;
    const int q0  = qt * BQ;
    const int tid = threadIdx.x;
    const int warp = tid >> 5;

    const bf16* Qgh = g_Qh + (size_t)(b*NH  + h  )*SEQ*HD;
    const bf16* Qgl = g_Ql + (size_t)(b*NH  + h  )*SEQ*HD;
    const bf16* Kgh = g_Kh + (size_t)(b*NKV + kvh)*SEQ*HD;
    const bf16* Kgl = g_Kl + (size_t)(b*NKV + kvh)*SEQ*HD;
    const bf16* Vgh = g_Vh + (size_t)(b*NKV + kvh)*SEQ*HD;
    const bf16* Vgl = g_Vl + (size_t)(b*NKV + kvh)*SEQ*HD;

    #pragma unroll
    for (int i = 0; i < 8; i++) {
        int c = tid + i*256;
        int t = c >> 10, idx = c & 1023;
        int row = idx >> 4, cc = idx & 15;
        const bf16* src = (t == 0 ? Qgh : Qgl) + (size_t)(q0+row)*HD + cc*8;
        bf16* dst = (t == 0 ? Qh : Ql) + row*LDA + cc*8;
        *(uint4*)dst = *(const uint4*)src;
    }
    #pragma unroll
    for (int i = 0; i < 8; i++) {
        int idx = tid + i*256;
        int row = idx >> 5, c4 = idx & 31;
        *(float4*)&Os[row*HD + c4*4] = make_float4(0.f,0.f,0.f,0.f);
    }

    const int r = tid >> 2;
    const int g = tid & 3;
    float m_r = -INFINITY, l_r = 0.f;

    for (int j = 0; j <= qt; j++) {
        __syncthreads();
        #pragma unroll
        for (int i = 0; i < 16; i++) {
            int c = tid + i*256;
            int t = c >> 10, idx = c & 1023;
            int row = idx >> 4, cc = idx & 15;
            const bf16* src;
            bf16* dst;
            if      (t == 0) { src = Kgh; dst = Kh; }
            else if (t == 1) { src = Kgl; dst = Kl; }
            else if (t == 2) { src = Vgh; dst = Vh; }
            else             { src = Vgl; dst = Vl; }
            *(uint4*)(dst + row*LDA + cc*8) =
                *(const uint4*)(src + (size_t)(j*BKV+row)*HD + cc*8);
        }
        __syncthreads();

        {
            const int wr0 = (warp >> 1) * 16;
            const int wc0 = (warp & 1) * 32;
            CF sc[2];
            wmma::fill_fragment(sc[0], 0.f);
            wmma::fill_fragment(sc[1], 0.f);
            #pragma unroll
            for (int ks = 0; ks < HD; ks += 16) {
                AF ah, al;
                wmma::load_matrix_sync(ah, Qh + wr0*LDA + ks, LDA);
                wmma::load_matrix_sync(al, Ql + wr0*LDA + ks, LDA);
                #pragma unroll
                for (int jj = 0; jj < 2; jj++) {
                    BFc bh, bl;
                    wmma::load_matrix_sync(bh, Kh + (wc0 + jj*16)*LDA + ks, LDA);
                    wmma::load_matrix_sync(bl, Kl + (wc0 + jj*16)*LDA + ks, LDA);
                    wmma::mma_sync(sc[jj], al, bh, sc[jj]);
                    wmma::mma_sync(sc[jj], ah, bl, sc[jj]);
                    wmma::mma_sync(sc[jj], ah, bh, sc[jj]);
                }
            }
            wmma::store_matrix_sync(&Ss[wr0*64 + wc0     ], sc[0], 64, wmma::mem_row_major);
            wmma::store_matrix_sync(&Ss[wr0*64 + wc0 + 16], sc[1], 64, wmma::mem_row_major);
        }
        __syncthreads();

        {
            const bool diag = (j == qt);
            float mx = -INFINITY;
            #pragma unroll
            for (int c = g; c < BKV; c += 4) {
                float v = Ss[r*64 + c];
                if (diag && (j*BKV + c > q0 + r)) v = -INFINITY;
                mx = fmaxf(mx, v);
            }
            mx = fmaxf(mx, __shfl_xor_sync(0xffffffffu, mx, 1));
            mx = fmaxf(mx, __shfl_xor_sync(0xffffffffu, mx, 2));
            float m_new = fmaxf(m_r, mx);
            float alpha = expf(m_r - m_new);
            float sum = 0.f;
            #pragma unroll
            for (int c = g; c < BKV; c += 4) {
                float v = Ss[r*64 + c];
                float p = (diag && (j*BKV + c > q0 + r)) ? 0.f : expf(v - m_new);
                bf16 ph, pl;
                bf16_split(p, ph, pl);
                Ph[r*LDP + c] = ph;
                Pl[r*LDP + c] = pl;
                sum += p;
            }
            sum += __shfl_xor_sync(0xffffffffu, sum, 1);
            sum += __shfl_xor_sync(0xffffffffu, sum, 2);
            l_r = l_r * alpha + sum;
            m_r = m_new;
            #pragma unroll
            for (int d = g; d < HD; d += 4)
                Os[r*HD + d] *= alpha;
        }
        __syncthreads();

        {
            const int wr0 = (warp >> 1) * 16;
            const int wc0 = (warp & 1) * 64;
            CF oc[4];
            #pragma unroll
            for (int jj = 0; jj < 4; jj++)
                wmma::load_matrix_sync(oc[jj], &Os[wr0*HD + wc0 + jj*16], HD,
                                       wmma::mem_row_major);
            #pragma unroll
            for (int ks = 0; ks < BKV; ks += 16) {
                AF ah, al;
                wmma::load_matrix_sync(ah, Ph + wr0*LDP + ks, LDP);
                wmma::load_matrix_sync(al, Pl + wr0*LDP + ks, LDP);
                #pragma unroll
                for (int jj = 0; jj < 4; jj++) {
                    BFr bh, bl;
                    wmma::load_matrix_sync(bh, Vh + ks*LDA + wc0 + jj*16, LDA);
                    wmma::load_matrix_sync(bl, Vl + ks*LDA + wc0 + jj*16, LDA);
                    wmma::mma_sync(oc[jj], al, bh, oc[jj]);
                    wmma::mma_sync(oc[jj], ah, bl, oc[jj]);
                    wmma::mma_sync(oc[jj], ah, bh, oc[jj]);
                }
            }
            #pragma unroll
            for (int jj = 0; jj < 4; jj++)
                wmma::store_matrix_sync(&Os[wr0*HD + wc0 + jj*16], oc[jj], HD,
                                        wmma::mem_row_major);
        }
    }
    __syncthreads();

    {
        float inv = 1.f / l_r;
        size_t ob = ((size_t)(b*SEQ + q0 + r))*QDIM + h*HD;
        #pragma unroll
        for (int d = g; d < HD; d += 4) {
            float v = Os[r*HD + d] * inv;
            bf16 hv, lv;
            bf16_split(v, hv, lv);
            g_Ah[ob + d] = hv;
            g_Al[ob + d] = lv;
        }
    }
}

// ---------------------------------------------------------------------------
// launch
// ---------------------------------------------------------------------------
extern "C" void kernel_launch(void* const* d_in, const int* in_sizes, int n_in,
                              void* d_out, int out_size)
{
    (void)in_sizes; (void)n_in; (void)out_size;
    const float* hs   = (const float*)d_in[0];
    const float* cosp = (const float*)d_in[1];
    const float* sinp = (const float*)d_in[2];
    const float* Wq   = (const float*)d_in[3];
    const float* bq   = (const float*)d_in[4];
    const float* Wk   = (const float*)d_in[5];
    const float* bk   = (const float*)d_in[6];
    const float* Wv   = (const float*)d_in[7];
    const float* bv   = (const float*)d_in[8];
    const float* Wo   = (const float*)d_in[9];
    float* out = (float*)d_out;

    float *Cqkv;
    bf16 *hsh, *hsl, *Wch, *Wcl, *Woh, *Wol, *Ah, *Al;
    cudaGetSymbolAddress((void**)&Cqkv, g_Cqkv);
    cudaGetSymbolAddress((void**)&hsh, g_hsh);
    cudaGetSymbolAddress((void**)&hsl, g_hsl);
    cudaGetSymbolAddress((void**)&Wch, g_Wch);
    cudaGetSymbolAddress((void**)&Wcl, g_Wcl);
    cudaGetSymbolAddress((void**)&Woh, g_Woh);
    cudaGetSymbolAddress((void**)&Wol, g_Wol);
    cudaGetSymbolAddress((void**)&Ah,  g_Ah);
    cudaGetSymbolAddress((void**)&Al,  g_Al);

    cudaFuncSetAttribute(gemm_v2,
                         cudaFuncAttributeMaxDynamicSharedMemorySize,
                         SMEM2_BYTES);
    cudaFuncSetAttribute(attn_kernel,
                         cudaFuncAttributeMaxDynamicSharedMemorySize,
                         ATTN_SMEM_BYTES);

    auto split = [&](const float* src, bf16* hi, bf16* lo, size_t n) {
        size_t n4 = n / 4;
        split_bf16<<<(unsigned)((n4 + 255)/256), 256>>>(
            (const float4*)src, (__nv_bfloat162*)hi, (__nv_bfloat162*)lo, n4);
    };
    split(hs, hsh, hsl, (size_t)M_TOK*HIDDEN);
    split(Wq, Wch,                              Wcl,                              (size_t)QDIM*HIDDEN);
    split(Wk, Wch + (size_t)QDIM*HIDDEN,        Wcl + (size_t)QDIM*HIDDEN,        (size_t)KVDIM*HIDDEN);
    split(Wv, Wch + (size_t)(QDIM+KVDIM)*HIDDEN, Wcl + (size_t)(QDIM+KVDIM)*HIDDEN, (size_t)KVDIM*HIDDEN);
    split(Wo, Woh, Wol, (size_t)HIDDEN*QDIM);

    // combined QKV projection: [4096, 4608] = [4096, 3584] @ Wc^T
    gemm_v2<<<dim3(NDIMC/BN2, M_TOK/BM2), 512, SMEM2_BYTES>>>(
        hsh, hsl, Wch, Wcl, Cqkv, M_TOK, NDIMC, HIDDEN);
    pack_rope<<<M_TOK, 256>>>(Cqkv, bq, bk, bv, cosp, sinp);
    attn_kernel<<<dim3(SEQ/BQ, NH, BATCH), 256, ATTN_SMEM_BYTES>>>();
    gemm_v2<<<dim3(QDIM/BN2, M_TOK/BM2), 512, SMEM2_BYTES>>>(
        Ah, Al, Woh, Wol, out, M_TOK, QDIM, HIDDEN);
}

// round 7
// speedup vs baseline: 4.2165x; 1.4416x over previous
#include <cuda_runtime.h>
#include <cuda_bf16.h>
#include <mma.h>
#include <math.h>
#include <cstdint>
#include <cstddef>

using namespace nvcuda;

#define HIDDEN 3584
#define NH 28
#define NKV 4
#define HD 128
#define NREP 7
#define BATCH 2
#define SEQ 2048
#define M_TOK (BATCH*SEQ)   // 4096
#define QDIM (NH*HD)        // 3584
#define KVDIM (NKV*HD)      // 512
#define NDIMC (QDIM + 2*KVDIM)   // 4608

typedef __nv_bfloat16 bf16;

// ---------------------------------------------------------------------------
// Scratch
// ---------------------------------------------------------------------------
__device__ float g_Cqkv[(size_t)M_TOK*NDIMC];

__device__ __align__(128) bf16 g_hsh[(size_t)M_TOK*HIDDEN];
__device__ __align__(128) bf16 g_hsl[(size_t)M_TOK*HIDDEN];
__device__ __align__(128) bf16 g_Wch[(size_t)NDIMC*HIDDEN];
__device__ __align__(128) bf16 g_Wcl[(size_t)NDIMC*HIDDEN];
__device__ __align__(128) bf16 g_Woh[(size_t)HIDDEN*QDIM];
__device__ __align__(128) bf16 g_Wol[(size_t)HIDDEN*QDIM];

__device__ __align__(128) bf16 g_Qh[(size_t)M_TOK*QDIM];   // [B][NH][S][D]
__device__ __align__(128) bf16 g_Ql[(size_t)M_TOK*QDIM];
__device__ __align__(128) bf16 g_Kh[(size_t)M_TOK*KVDIM];  // [B][NKV][S][D]
__device__ __align__(128) bf16 g_Kl[(size_t)M_TOK*KVDIM];
__device__ __align__(128) bf16 g_Vh[(size_t)M_TOK*KVDIM];
__device__ __align__(128) bf16 g_Vl[(size_t)M_TOK*KVDIM];
__device__ __align__(128) bf16 g_Ah[(size_t)M_TOK*QDIM];
__device__ __align__(128) bf16 g_Al[(size_t)M_TOK*QDIM];

// ---------------------------------------------------------------------------
// helpers
// ---------------------------------------------------------------------------
__device__ __forceinline__ void bf16_split(float x, bf16& hi, bf16& lo) {
    hi = __float2bfloat16(x);
    lo = __float2bfloat16(x - __bfloat162float(hi));
}
__device__ __forceinline__ uint32_t smem_u32(const void* p) {
    return (uint32_t)__cvta_generic_to_shared(p);
}
__device__ __forceinline__ void cp_async16_sm(uint32_t s, const void* g) {
    asm volatile("cp.async.cg.shared.global [%0], [%1], 16;\n"
                 :: "r"(s), "l"(g));
}
__device__ __forceinline__ void ldsm_x4(uint32_t r[4], uint32_t addr) {
    asm volatile("ldmatrix.sync.aligned.m8n8.x4.shared.b16 {%0,%1,%2,%3}, [%4];"
        : "=r"(r[0]), "=r"(r[1]), "=r"(r[2]), "=r"(r[3]) : "r"(addr));
}
__device__ __forceinline__ void ldsm_x2(uint32_t r[2], uint32_t addr) {
    asm volatile("ldmatrix.sync.aligned.m8n8.x2.shared.b16 {%0,%1}, [%2];"
        : "=r"(r[0]), "=r"(r[1]) : "r"(addr));
}
__device__ __forceinline__ void ldsm_x2t(uint32_t r[2], uint32_t addr) {
    asm volatile("ldmatrix.sync.aligned.m8n8.x2.trans.shared.b16 {%0,%1}, [%2];"
        : "=r"(r[0]), "=r"(r[1]) : "r"(addr));
}
__device__ __forceinline__ void mma16816(float d[4], const uint32_t a[4],
                                         const uint32_t b[2]) {
    asm volatile(
        "mma.sync.aligned.m16n8k16.row.col.f32.bf16.bf16.f32 "
        "{%0,%1,%2,%3}, {%4,%5,%6,%7}, {%8,%9}, {%0,%1,%2,%3};"
        : "+f"(d[0]), "+f"(d[1]), "+f"(d[2]), "+f"(d[3])
        : "r"(a[0]), "r"(a[1]), "r"(a[2]), "r"(a[3]), "r"(b[0]), "r"(b[1]));
}
__device__ __forceinline__ uint32_t pack_bf2(float lo, float hi) {
    __nv_bfloat162 v(__float2bfloat16(lo), __float2bfloat16(hi));
    return *(uint32_t*)&v;
}

// elementwise split fp32 -> bf16 hi/lo
__global__ void __launch_bounds__(256) split_bf16(
    const float4* __restrict__ src, __nv_bfloat162* __restrict__ hi,
    __nv_bfloat162* __restrict__ lo, size_t n4)
{
    size_t i = (size_t)blockIdx.x*blockDim.x + threadIdx.x;
    if (i >= n4) return;
    float4 v = src[i];
    bf16 hx, lx, hy, ly, hz, lz, hw, lw;
    bf16_split(v.x, hx, lx);
    bf16_split(v.y, hy, ly);
    bf16_split(v.z, hz, lz);
    bf16_split(v.w, hw, lw);
    hi[2*i]   = __nv_bfloat162(hx, hy);
    hi[2*i+1] = __nv_bfloat162(hz, hw);
    lo[2*i]   = __nv_bfloat162(lx, ly);
    lo[2*i+1] = __nv_bfloat162(lz, lw);
}

// ---------------------------------------------------------------------------
// 3xBF16 WMMA GEMM v2 (unchanged from R6)
// ---------------------------------------------------------------------------
#define BM2 256
#define BN2 128
#define BK2 32
#define LDT2 40
#define OFF_AH 0
#define OFF_AL (BM2*LDT2)
#define OFF_BH (2*BM2*LDT2)
#define OFF_BL (2*BM2*LDT2 + BN2*LDT2)
#define STAGE2_HALFS (2*BM2*LDT2 + 2*BN2*LDT2)
#define NSTAGE2 3
#define SMEM2_BYTES (NSTAGE2*STAGE2_HALFS*2)

typedef wmma::fragment<wmma::matrix_a,16,16,16,bf16,wmma::row_major> AF;
typedef wmma::fragment<wmma::matrix_b,16,16,16,bf16,wmma::col_major> BFc;
typedef wmma::fragment<wmma::accumulator,16,16,16,float> CF;

__global__ void __launch_bounds__(512) gemm_v2(
    const bf16* __restrict__ Ah, const bf16* __restrict__ Al,
    const bf16* __restrict__ Wh, const bf16* __restrict__ Wl,
    float* __restrict__ C, int M, int N, int K)
{
    extern __shared__ __align__(16) bf16 sm[];
    const uint32_t smb = smem_u32(sm);
    const int tid  = threadIdx.x;
    const int warp = tid >> 5;
    const int wr   = warp >> 2;
    const int wc   = warp & 3;
    const int bm   = blockIdx.y * BM2;
    const int bn   = blockIdx.x * BN2;

    CF acc[4][2];
    #pragma unroll
    for (int i = 0; i < 4; i++)
        #pragma unroll
        for (int j = 0; j < 2; j++)
            wmma::fill_fragment(acc[i][j], 0.0f);

    auto load_chunk = [&](int chunk, int slot) {
        const int k0 = chunk * BK2;
        const uint32_t base = smb + (uint32_t)(slot*STAGE2_HALFS*2);
        #pragma unroll
        for (int it = 0; it < 6; it++) {
            int c = tid + it*512;
            const bf16* g;
            uint32_t soff;
            if (c < 2048) {
                int t = c >> 10, idx = c & 1023;
                int row = idx >> 2, c16 = idx & 3;
                g = (t ? Al : Ah) + (size_t)(bm+row)*K + k0 + c16*8;
                soff = (uint32_t)(((t ? OFF_AL : OFF_AH) + row*LDT2 + c16*8) * 2);
            } else {
                int d = c - 2048;
                int t = d >> 9, idx = d & 511;
                int row = idx >> 2, c16 = idx & 3;
                g = (t ? Wl : Wh) + (size_t)(bn+row)*K + k0 + c16*8;
                soff = (uint32_t)(((t ? OFF_BL : OFF_BH) + row*LDT2 + c16*8) * 2);
            }
            cp_async16_sm(base + soff, g);
        }
        asm volatile("cp.async.commit_group;" ::: "memory");
    };

    const int T = K / BK2;
    load_chunk(0, 0);
    load_chunk(1, 1);

    for (int i = 0; i < T; i++) {
        const int slot = i % NSTAGE2;
        if (i + 1 < T) asm volatile("cp.async.wait_group 1;" ::: "memory");
        else           asm volatile("cp.async.wait_group 0;" ::: "memory");
        __syncthreads();
        if (i + 2 < T) load_chunk(i + 2, (i + 2) % NSTAGE2);

        const bf16* st = sm + slot*STAGE2_HALFS;
        #pragma unroll
        for (int ks = 0; ks < 2; ks++) {
            const int kofs = ks*16;
            AF ah[4], al[4];
            #pragma unroll
            for (int i4 = 0; i4 < 4; i4++) {
                wmma::load_matrix_sync(ah[i4], st + OFF_AH + (wr*64 + i4*16)*LDT2 + kofs, LDT2);
                wmma::load_matrix_sync(al[i4], st + OFF_AL + (wr*64 + i4*16)*LDT2 + kofs, LDT2);
            }
            #pragma unroll
            for (int jj = 0; jj < 2; jj++) {
                BFc bh, bl;
                wmma::load_matrix_sync(bh, st + OFF_BH + (wc*32 + jj*16)*LDT2 + kofs, LDT2);
                wmma::load_matrix_sync(bl, st + OFF_BL + (wc*32 + jj*16)*LDT2 + kofs, LDT2);
                #pragma unroll
                for (int i4 = 0; i4 < 4; i4++) {
                    wmma::mma_sync(acc[i4][jj], al[i4], bh, acc[i4][jj]);
                    wmma::mma_sync(acc[i4][jj], ah[i4], bl, acc[i4][jj]);
                    wmma::mma_sync(acc[i4][jj], ah[i4], bh, acc[i4][jj]);
                }
            }
        }
    }

    #pragma unroll
    for (int i4 = 0; i4 < 4; i4++)
        #pragma unroll
        for (int jj = 0; jj < 2; jj++) {
            int row = bm + wr*64 + i4*16;
            int col = bn + wc*32 + jj*16;
            wmma::store_matrix_sync(&C[(size_t)row*N + col], acc[i4][jj], N,
                                    wmma::mem_row_major);
        }
}

// ---------------------------------------------------------------------------
// bias + RoPE + transpose; folds (1/sqrt(128))*log2(e) into Q.
// ---------------------------------------------------------------------------
__global__ void __launch_bounds__(256) pack_rope(
    const float* __restrict__ Cqkv,
    const float* __restrict__ bq, const float* __restrict__ bk,
    const float* __restrict__ bv,
    const float* __restrict__ cosp, const float* __restrict__ sinp)
{
    const int token = blockIdx.x;
    const int b = token / SEQ, s = token % SEQ;
    __shared__ float cs[HD], sn[HD];
    if (threadIdx.x < HD) {
        cs[threadIdx.x] = cosp[(size_t)token*HD + threadIdx.x];
        sn[threadIdx.x] = sinp[(size_t)token*HD + threadIdx.x];
    }
    __syncthreads();
    // 128^-0.5 * log2(e): scores computed in exp2 domain
    const float scaling = 0.08838834764831845f * 1.4426950408889634f;
    const float* Crow = Cqkv + (size_t)token*NDIMC;

    for (int i = threadIdx.x; i < NH*64; i += blockDim.x) {
        int h = i >> 6, d = i & 63;
        float x1 = Crow[h*HD + d]      + bq[h*HD + d];
        float x2 = Crow[h*HD + d + 64] + bq[h*HD + d + 64];
        float o1 = (x1*cs[d]      - x2*sn[d])      * scaling;
        float o2 = (x2*cs[d + 64] + x1*sn[d + 64]) * scaling;
        size_t ob = ((size_t)(b*NH + h)*SEQ + s)*HD;
        bf16 h1, l1, h2, l2;
        bf16_split(o1, h1, l1);
        bf16_split(o2, h2, l2);
        g_Qh[ob + d] = h1;      g_Ql[ob + d] = l1;
        g_Qh[ob + d + 64] = h2; g_Ql[ob + d + 64] = l2;
    }
    for (int i = threadIdx.x; i < NKV*64; i += blockDim.x) {
        int h = i >> 6, d = i & 63;
        float x1 = Crow[QDIM + h*HD + d]      + bk[h*HD + d];
        float x2 = Crow[QDIM + h*HD + d + 64] + bk[h*HD + d + 64];
        float o1 = x1*cs[d]      - x2*sn[d];
        float o2 = x2*cs[d + 64] + x1*sn[d + 64];
        size_t ob = ((size_t)(b*NKV + h)*SEQ + s)*HD;
        bf16 h1, l1, h2, l2;
        bf16_split(o1, h1, l1);
        bf16_split(o2, h2, l2);
        g_Kh[ob + d] = h1;      g_Kl[ob + d] = l1;
        g_Kh[ob + d + 64] = h2; g_Kl[ob + d + 64] = l2;
    }
    for (int i = threadIdx.x; i < KVDIM; i += blockDim.x) {
        int h = i >> 7, d = i & 127;
        float v = Crow[QDIM + KVDIM + i] + bv[i];
        size_t ob = ((size_t)(b*NKV + h)*SEQ + s)*HD + d;
        bf16 hv, lv;
        bf16_split(v, hv, lv);
        g_Vh[ob] = hv; g_Vl[ob] = lv;
    }
}

// ---------------------------------------------------------------------------
// FlashAttention-2 style causal GQA attention, mma.sync m16n8k16, 3xBF16.
// BQ=128, BKV=64, D=128. 8 warps; warp w owns Q rows [w*16, w*16+16).
// O/S/P/m/l in registers. Q in smem (hi/lo), K/V double-buffered cp.async.
// ---------------------------------------------------------------------------
#define FBQ 128
#define FBKV 64
#define FLD 136                       // smem stride (halves), 272B
#define FQT_HALFS (128*FLD)           // one Q tensor
#define FKV_HALFS (64*FLD)            // one K/V tensor
#define FSTAGE_HALFS (4*FKV_HALFS)    // Kh,Kl,Vh,Vl
#define FQ_BYTES (2*FQT_HALFS*2)
#define FSTAGE_BYTES (FSTAGE_HALFS*2)
#define FKV_BYTES (FKV_HALFS*2)
#define FATTN_SMEM (FQ_BYTES + 2*FSTAGE_BYTES)   // 208896

__global__ void __launch_bounds__(256) attn_fa2()
{
    extern __shared__ __align__(16) char smraw[];
    const uint32_t smb = smem_u32(smraw);
    const uint32_t sQh = smb;
    const uint32_t sQl = smb + FQT_HALFS*2;

    const int qt  = blockIdx.x;          // 0..15
    const int h   = blockIdx.y;
    const int b   = blockIdx.z;
    const int kvh = h / NREP;
    const int q0  = qt * FBQ;
    const int tid = threadIdx.x;
    const int warp = tid >> 5;
    const int lane = tid & 31;
    const int R = warp * 16;             // warp's Q-row base within tile

    const bf16* Qgh = g_Qh + (size_t)(b*NH  + h  )*SEQ*HD;
    const bf16* Qgl = g_Ql + (size_t)(b*NH  + h  )*SEQ*HD;
    const bf16* Kgh = g_Kh + (size_t)(b*NKV + kvh)*SEQ*HD;
    const bf16* Kgl = g_Kl + (size_t)(b*NKV + kvh)*SEQ*HD;
    const bf16* Vgh = g_Vh + (size_t)(b*NKV + kvh)*SEQ*HD;
    const bf16* Vgl = g_Vl + (size_t)(b*NKV + kvh)*SEQ*HD;

    // ---- load Q tile hi/lo into smem (once) ----
    {
        bf16* qsm = (bf16*)smraw;
        #pragma unroll
        for (int it = 0; it < 16; it++) {
            int c = tid + it*256;        // 4096 = 2 tensors x 128 rows x 16
            int t = c >> 11, idx = c & 2047;
            int row = idx >> 4, c16 = idx & 15;
            const bf16* src = (t ? Qgl : Qgh) + (size_t)(q0+row)*HD + c16*8;
            *(uint4*)(qsm + t*FQT_HALFS + row*FLD + c16*8) = *(const uint4*)src;
        }
    }

    auto load_kv = [&](int j, int s) {
        const uint32_t base = smb + FQ_BYTES + (uint32_t)(s*FSTAGE_BYTES);
        #pragma unroll
        for (int it = 0; it < 16; it++) {
            int c = tid + it*256;        // 4096 = 4 tensors x 64 rows x 16
            int t = c >> 10, idx = c & 1023;
            int row = idx >> 4, c16 = idx & 15;
            const bf16* src;
            if      (t == 0) src = Kgh;
            else if (t == 1) src = Kgl;
            else if (t == 2) src = Vgh;
            else             src = Vgl;
            cp_async16_sm(base + (uint32_t)((t*FKV_HALFS + row*FLD + c16*8)*2),
                          src + (size_t)(j*FBKV+row)*HD + c16*8);
        }
        asm volatile("cp.async.commit_group;" ::: "memory");
    };

    const int nt = 2*qt + 2;
    load_kv(0, 0);
    __syncthreads();                     // Q smem ready (also covers stage usage)

    float oc[16][4];
    #pragma unroll
    for (int i = 0; i < 16; i++)
        #pragma unroll
        for (int c = 0; c < 4; c++) oc[i][c] = 0.f;
    float m_lo = -INFINITY, m_hi = -INFINITY;
    float l_lo = 0.f, l_hi = 0.f;

    const int row_lo = q0 + R + (lane >> 2);
    const int row_hi = row_lo + 8;

    for (int j = 0; j < nt; j++) {
        const int s = j & 1;
        asm volatile("cp.async.wait_group 0;" ::: "memory");
        __syncthreads();
        if (j + 1 < nt) load_kv(j + 1, s ^ 1);

        if (j*FBKV > q0 + R + 15) continue;    // warp fully masked on this tile

        const uint32_t stg = smb + FQ_BYTES + (uint32_t)(s*FSTAGE_BYTES);
        const uint32_t sKh = stg;
        const uint32_t sKl = stg + FKV_BYTES;
        const uint32_t sVh = stg + 2*FKV_BYTES;
        const uint32_t sVl = stg + 3*FKV_BYTES;

        // ---- S = Q @ K^T : 128(warp:16) x 64, k=128 ----
        float sc[8][4];
        #pragma unroll
        for (int nb = 0; nb < 8; nb++)
            #pragma unroll
            for (int c = 0; c < 4; c++) sc[nb][c] = 0.f;

        #pragma unroll
        for (int ks = 0; ks < 8; ks++) {
            uint32_t qh[4], ql[4];
            int qrow = R + (lane & 7) + ((lane >> 3) & 1)*8;
            int qcol = ks*16 + ((lane >> 4) & 1)*8;
            ldsm_x4(qh, sQh + (uint32_t)((qrow*FLD + qcol)*2));
            ldsm_x4(ql, sQl + (uint32_t)((qrow*FLD + qcol)*2));
            #pragma unroll
            for (int nb = 0; nb < 8; nb++) {
                uint32_t kh[2], kl[2];
                int krow = nb*8 + (lane & 7);
                int kcol = ks*16 + ((lane >> 3) & 1)*8;
                ldsm_x2(kh, sKh + (uint32_t)((krow*FLD + kcol)*2));
                ldsm_x2(kl, sKl + (uint32_t)((krow*FLD + kcol)*2));
                mma16816(sc[nb], ql, kh);
                mma16816(sc[nb], qh, kl);
                mma16816(sc[nb], qh, kh);
            }
        }

        // ---- online softmax in registers ----
        const bool masked = (j*FBKV + 63 > q0 + R);
        const int cb = j*FBKV + (lane & 3)*2;
        float tmlo = -INFINITY, tmhi = -INFINITY;
        if (!masked) {
            #pragma unroll
            for (int nb = 0; nb < 8; nb++) {
                tmlo = fmaxf(tmlo, fmaxf(sc[nb][0], sc[nb][1]));
                tmhi = fmaxf(tmhi, fmaxf(sc[nb][2], sc[nb][3]));
            }
        } else {
            #pragma unroll
            for (int nb = 0; nb < 8; nb++) {
                int c0 = cb + nb*8, c1 = c0 + 1;
                if (c0 <= row_lo) tmlo = fmaxf(tmlo, sc[nb][0]);
                if (c1 <= row_lo) tmlo = fmaxf(tmlo, sc[nb][1]);
                if (c0 <= row_hi) tmhi = fmaxf(tmhi, sc[nb][2]);
                if (c1 <= row_hi) tmhi = fmaxf(tmhi, sc[nb][3]);
            }
        }
        tmlo = fmaxf(tmlo, __shfl_xor_sync(0xffffffffu, tmlo, 1));
        tmlo = fmaxf(tmlo, __shfl_xor_sync(0xffffffffu, tmlo, 2));
        tmhi = fmaxf(tmhi, __shfl_xor_sync(0xffffffffu, tmhi, 1));
        tmhi = fmaxf(tmhi, __shfl_xor_sync(0xffffffffu, tmhi, 2));

        float mn_lo = fmaxf(m_lo, tmlo);
        float mn_hi = fmaxf(m_hi, tmhi);
        float alpha_lo = exp2f(m_lo - mn_lo);
        float alpha_hi = exp2f(m_hi - mn_hi);
        m_lo = mn_lo; m_hi = mn_hi;
        #pragma unroll
        for (int nb = 0; nb < 16; nb++) {
            oc[nb][0] *= alpha_lo; oc[nb][1] *= alpha_lo;
            oc[nb][2] *= alpha_hi; oc[nb][3] *= alpha_hi;
        }

        float slo = 0.f, shi = 0.f;
        #pragma unroll
        for (int nb = 0; nb < 8; nb++) {
            float p0 = exp2f(sc[nb][0] - mn_lo);
            float p1 = exp2f(sc[nb][1] - mn_lo);
            float p2 = exp2f(sc[nb][2] - mn_hi);
            float p3 = exp2f(sc[nb][3] - mn_hi);
            if (masked) {
                int c0 = cb + nb*8, c1 = c0 + 1;
                if (c0 > row_lo) p0 = 0.f;
                if (c1 > row_lo) p1 = 0.f;
                if (c0 > row_hi) p2 = 0.f;
                if (c1 > row_hi) p3 = 0.f;
            }
            sc[nb][0] = p0; sc[nb][1] = p1; sc[nb][2] = p2; sc[nb][3] = p3;
            slo += p0 + p1; shi += p2 + p3;
        }
        slo += __shfl_xor_sync(0xffffffffu, slo, 1);
        slo += __shfl_xor_sync(0xffffffffu, slo, 2);
        shi += __shfl_xor_sync(0xffffffffu, shi, 1);
        shi += __shfl_xor_sync(0xffffffffu, shi, 2);
        l_lo = l_lo * alpha_lo + slo;
        l_hi = l_hi * alpha_hi + shi;

        // ---- O += P @ V : 16 x 128, k=64 ----
        #pragma unroll
        for (int ks2 = 0; ks2 < 4; ks2++) {
            // repack P frags 2*ks2, 2*ks2+1 -> bf16 hi/lo A fragments
            uint32_t pah[4], pal[4];
            #pragma unroll
            for (int half = 0; half < 2; half++) {
                const float* f = sc[2*ks2 + half];
                bf16 h0, l0, h1, l1, h2, l2, h3, l3;
                bf16_split(f[0], h0, l0);
                bf16_split(f[1], h1, l1);
                bf16_split(f[2], h2, l2);
                bf16_split(f[3], h3, l3);
                pah[half*2 + 0] = pack_bf2(__bfloat162float(h0), __bfloat162float(h1));
                pah[half*2 + 1] = pack_bf2(__bfloat162float(h2), __bfloat162float(h3));
                pal[half*2 + 0] = pack_bf2(__bfloat162float(l0), __bfloat162float(l1));
                pal[half*2 + 1] = pack_bf2(__bfloat162float(l2), __bfloat162float(l3));
            }
            // wait: a-reg order must be {a0,a1,a2,a3} = (r,k0-7),(r+8,k0-7),(r,k8-15),(r+8,k8-15)
            // half0 gives a0,a1; half1 gives a2,a3 -- layout above already matches.
            #pragma unroll
            for (int nb = 0; nb < 16; nb++) {
                uint32_t vh[2], vl[2];
                int vrow = ks2*16 + (lane & 7) + ((lane >> 3) & 1)*8;
                int vcol = nb*8;
                ldsm_x2t(vh, sVh + (uint32_t)((vrow*FLD + vcol)*2));
                ldsm_x2t(vl, sVl + (uint32_t)((vrow*FLD + vcol)*2));
                mma16816(oc[nb], pal, vh);
                mma16816(oc[nb], pah, vl);
                mma16816(oc[nb], pah, vh);
            }
        }
    }

    // ---- epilogue: normalize, split hi/lo, store ----
    {
        float inv_lo = 1.f / l_lo;
        float inv_hi = 1.f / l_hi;
        size_t base_lo = ((size_t)(b*SEQ + row_lo))*QDIM + h*HD;
        size_t base_hi = ((size_t)(b*SEQ + row_hi))*QDIM + h*HD;
        #pragma unroll
        for (int nb = 0; nb < 16; nb++) {
            int n0 = nb*8 + (lane & 3)*2;
            float f0 = oc[nb][0]*inv_lo, f1 = oc[nb][1]*inv_lo;
            float f2 = oc[nb][2]*inv_hi, f3 = oc[nb][3]*inv_hi;
            bf16 h0, l0, h1, l1, h2, l2, h3, l3;
            bf16_split(f0, h0, l0);
            bf16_split(f1, h1, l1);
            bf16_split(f2, h2, l2);
            bf16_split(f3, h3, l3);
            *(uint32_t*)&g_Ah[base_lo + n0] = pack_bf2(__bfloat162float(h0), __bfloat162float(h1));
            *(uint32_t*)&g_Al[base_lo + n0] = pack_bf2(__bfloat162float(l0), __bfloat162float(l1));
            *(uint32_t*)&g_Ah[base_hi + n0] = pack_bf2(__bfloat162float(h2), __bfloat162float(h3));
            *(uint32_t*)&g_Al[base_hi + n0] = pack_bf2(__bfloat162float(l2), __bfloat162float(l3));
        }
    }
}

// ---------------------------------------------------------------------------
// launch
// ---------------------------------------------------------------------------
extern "C" void kernel_launch(void* const* d_in, const int* in_sizes, int n_in,
                              void* d_out, int out_size)
{
    (void)in_sizes; (void)n_in; (void)out_size;
    const float* hs   = (const float*)d_in[0];
    const float* cosp = (const float*)d_in[1];
    const float* sinp = (const float*)d_in[2];
    const float* Wq   = (const float*)d_in[3];
    const float* bq   = (const float*)d_in[4];
    const float* Wk   = (const float*)d_in[5];
    const float* bk   = (const float*)d_in[6];
    const float* Wv   = (const float*)d_in[7];
    const float* bv   = (const float*)d_in[8];
    const float* Wo   = (const float*)d_in[9];
    float* out = (float*)d_out;

    float *Cqkv;
    bf16 *hsh, *hsl, *Wch, *Wcl, *Woh, *Wol, *Ah, *Al;
    cudaGetSymbolAddress((void**)&Cqkv, g_Cqkv);
    cudaGetSymbolAddress((void**)&hsh, g_hsh);
    cudaGetSymbolAddress((void**)&hsl, g_hsl);
    cudaGetSymbolAddress((void**)&Wch, g_Wch);
    cudaGetSymbolAddress((void**)&Wcl, g_Wcl);
    cudaGetSymbolAddress((void**)&Woh, g_Woh);
    cudaGetSymbolAddress((void**)&Wol, g_Wol);
    cudaGetSymbolAddress((void**)&Ah,  g_Ah);
    cudaGetSymbolAddress((void**)&Al,  g_Al);

    cudaFuncSetAttribute(gemm_v2,
                         cudaFuncAttributeMaxDynamicSharedMemorySize,
                         SMEM2_BYTES);
    cudaFuncSetAttribute(attn_fa2,
                         cudaFuncAttributeMaxDynamicSharedMemorySize,
                         FATTN_SMEM);

    auto split = [&](const float* src, bf16* hi, bf16* lo, size_t n) {
        size_t n4 = n / 4;
        split_bf16<<<(unsigned)((n4 + 255)/256), 256>>>(
            (const float4*)src, (__nv_bfloat162*)hi, (__nv_bfloat162*)lo, n4);
    };
    split(hs, hsh, hsl, (size_t)M_TOK*HIDDEN);
    split(Wq, Wch,                               Wcl,                               (size_t)QDIM*HIDDEN);
    split(Wk, Wch + (size_t)QDIM*HIDDEN,         Wcl + (size_t)QDIM*HIDDEN,         (size_t)KVDIM*HIDDEN);
    split(Wv, Wch + (size_t)(QDIM+KVDIM)*HIDDEN, Wcl + (size_t)(QDIM+KVDIM)*HIDDEN, (size_t)KVDIM*HIDDEN);
    split(Wo, Woh, Wol, (size_t)HIDDEN*QDIM);

    gemm_v2<<<dim3(NDIMC/BN2, M_TOK/BM2), 512, SMEM2_BYTES>>>(
        hsh, hsl, Wch, Wcl, Cqkv, M_TOK, NDIMC, HIDDEN);
    pack_rope<<<M_TOK, 256>>>(Cqkv, bq, bk, bv, cosp, sinp);
    attn_fa2<<<dim3(SEQ/FBQ, NH, BATCH), 256, FATTN_SMEM>>>();
    gemm_v2<<<dim3(QDIM/BN2, M_TOK/BM2), 512, SMEM2_BYTES>>>(
        Ah, Al, Woh, Wol, out, M_TOK, QDIM, HIDDEN);
}

// round 8
// speedup vs baseline: 5.0097x; 1.1881x over previous
#include <cuda_runtime.h>
#include <cuda_bf16.h>
#include <mma.h>
#include <math.h>
#include <cstdint>
#include <cstddef>

using namespace nvcuda;

#define HIDDEN 3584
#define NH 28
#define NKV 4
#define HD 128
#define NREP 7
#define BATCH 2
#define SEQ 2048
#define M_TOK (BATCH*SEQ)   // 4096
#define QDIM (NH*HD)        // 3584
#define KVDIM (NKV*HD)      // 512
#define NDIMC (QDIM + 2*KVDIM)   // 4608

typedef __nv_bfloat16 bf16;

// ---------------------------------------------------------------------------
// Scratch
// ---------------------------------------------------------------------------
__device__ float g_Cqkv[(size_t)M_TOK*NDIMC];

__device__ __align__(128) bf16 g_hsh[(size_t)M_TOK*HIDDEN];
__device__ __align__(128) bf16 g_hsl[(size_t)M_TOK*HIDDEN];
__device__ __align__(128) bf16 g_Wch[(size_t)NDIMC*HIDDEN];
__device__ __align__(128) bf16 g_Wcl[(size_t)NDIMC*HIDDEN];
__device__ __align__(128) bf16 g_Woh[(size_t)HIDDEN*QDIM];
__device__ __align__(128) bf16 g_Wol[(size_t)HIDDEN*QDIM];

__device__ __align__(128) bf16 g_Qh[(size_t)M_TOK*QDIM];   // [B][NH][S][D]
__device__ __align__(128) bf16 g_Ql[(size_t)M_TOK*QDIM];
__device__ __align__(128) bf16 g_Kh[(size_t)M_TOK*KVDIM];  // [B][NKV][S][D]
__device__ __align__(128) bf16 g_Kl[(size_t)M_TOK*KVDIM];
__device__ __align__(128) bf16 g_Vh[(size_t)M_TOK*KVDIM];
__device__ __align__(128) bf16 g_Vl[(size_t)M_TOK*KVDIM];
__device__ __align__(128) bf16 g_Ah[(size_t)M_TOK*QDIM];
__device__ __align__(128) bf16 g_Al[(size_t)M_TOK*QDIM];

// ---------------------------------------------------------------------------
// helpers
// ---------------------------------------------------------------------------
__device__ __forceinline__ void bf16_split(float x, bf16& hi, bf16& lo) {
    hi = __float2bfloat16(x);
    lo = __float2bfloat16(x - __bfloat162float(hi));
}
__device__ __forceinline__ uint32_t smem_u32(const void* p) {
    return (uint32_t)__cvta_generic_to_shared(p);
}
__device__ __forceinline__ void cp_async16_sm(uint32_t s, const void* g) {
    asm volatile("cp.async.cg.shared.global [%0], [%1], 16;\n"
                 :: "r"(s), "l"(g));
}
__device__ __forceinline__ void ldsm_x4(uint32_t r[4], uint32_t addr) {
    asm volatile("ldmatrix.sync.aligned.m8n8.x4.shared.b16 {%0,%1,%2,%3}, [%4];"
        : "=r"(r[0]), "=r"(r[1]), "=r"(r[2]), "=r"(r[3]) : "r"(addr));
}
__device__ __forceinline__ void ldsm_x2(uint32_t r[2], uint32_t addr) {
    asm volatile("ldmatrix.sync.aligned.m8n8.x2.shared.b16 {%0,%1}, [%2];"
        : "=r"(r[0]), "=r"(r[1]) : "r"(addr));
}
__device__ __forceinline__ void ldsm_x2t(uint32_t r[2], uint32_t addr) {
    asm volatile("ldmatrix.sync.aligned.m8n8.x2.trans.shared.b16 {%0,%1}, [%2];"
        : "=r"(r[0]), "=r"(r[1]) : "r"(addr));
}
__device__ __forceinline__ void mma16816(float d[4], const uint32_t a[4],
                                         const uint32_t b[2]) {
    asm volatile(
        "mma.sync.aligned.m16n8k16.row.col.f32.bf16.bf16.f32 "
        "{%0,%1,%2,%3}, {%4,%5,%6,%7}, {%8,%9}, {%0,%1,%2,%3};"
        : "+f"(d[0]), "+f"(d[1]), "+f"(d[2]), "+f"(d[3])
        : "r"(a[0]), "r"(a[1]), "r"(a[2]), "r"(a[3]), "r"(b[0]), "r"(b[1]));
}
__device__ __forceinline__ uint32_t pack_bf2(float lo, float hi) {
    __nv_bfloat162 v(__float2bfloat16(lo), __float2bfloat16(hi));
    return *(uint32_t*)&v;
}

// elementwise split fp32 -> bf16 hi/lo
__global__ void __launch_bounds__(256) split_bf16(
    const float4* __restrict__ src, __nv_bfloat162* __restrict__ hi,
    __nv_bfloat162* __restrict__ lo, size_t n4)
{
    size_t i = (size_t)blockIdx.x*blockDim.x + threadIdx.x;
    if (i >= n4) return;
    float4 v = src[i];
    bf16 hx, lx, hy, ly, hz, lz, hw, lw;
    bf16_split(v.x, hx, lx);
    bf16_split(v.y, hy, ly);
    bf16_split(v.z, hz, lz);
    bf16_split(v.w, hw, lw);
    hi[2*i]   = __nv_bfloat162(hx, hy);
    hi[2*i+1] = __nv_bfloat162(hz, hw);
    lo[2*i]   = __nv_bfloat162(lx, ly);
    lo[2*i+1] = __nv_bfloat162(lz, lw);
}

// ---------------------------------------------------------------------------
// 3xBF16 WMMA GEMM v3: C[M,N] = (Ah+Al)[M,K] @ (Wh+Wl)[N,K]^T
// BM=256 BN=128 BK=64, 2-stage cp.async (221KB), 8 warps, warp tile 64x64.
// ---------------------------------------------------------------------------
#define BM3 256
#define BN3 128
#define BK3 64
#define LDT3 72                              // padded smem row stride (halfs)
#define OFF3_AH 0
#define OFF3_AL (BM3*LDT3)                   // 18432
#define OFF3_BH (2*BM3*LDT3)                 // 36864
#define OFF3_BL (2*BM3*LDT3 + BN3*LDT3)      // 46080
#define STAGE3_HALFS (2*BM3*LDT3 + 2*BN3*LDT3)   // 55296
#define SMEM3_BYTES (2*STAGE3_HALFS*2)           // 221184

typedef wmma::fragment<wmma::matrix_a,16,16,16,bf16,wmma::row_major> AF;
typedef wmma::fragment<wmma::matrix_b,16,16,16,bf16,wmma::col_major> BFc;
typedef wmma::fragment<wmma::accumulator,16,16,16,float> CF;

__global__ void __launch_bounds__(256,1) gemm_v3(
    const bf16* __restrict__ Ah, const bf16* __restrict__ Al,
    const bf16* __restrict__ Wh, const bf16* __restrict__ Wl,
    float* __restrict__ C, int M, int N, int K)
{
    extern __shared__ __align__(16) bf16 sm[];
    const uint32_t smb = smem_u32(sm);
    const int tid  = threadIdx.x;
    const int warp = tid >> 5;
    const int wr   = warp >> 1;        // 0..3 : 64-row band
    const int wc   = warp & 1;         // 0..1 : 64-col band
    const int bm   = blockIdx.y * BM3;
    const int bn   = blockIdx.x * BN3;

    CF acc[4][4];
    #pragma unroll
    for (int i = 0; i < 4; i++)
        #pragma unroll
        for (int j = 0; j < 4; j++)
            wmma::fill_fragment(acc[i][j], 0.0f);

    auto load_chunk = [&](int chunk, int slot) {
        const int k0 = chunk * BK3;
        const uint32_t base = smb + (uint32_t)(slot*STAGE3_HALFS*2);
        #pragma unroll
        for (int it = 0; it < 24; it++) {
            int c = tid + it*256;              // 0..6143 16B transfers
            const bf16* g;
            uint32_t soff;
            if (c < 4096) {                    // A hi/lo: 2 x 2048 (256 rows x 8)
                int t = c >> 11, idx = c & 2047;
                int row = idx >> 3, c16 = idx & 7;
                g = (t ? Al : Ah) + (size_t)(bm+row)*K + k0 + c16*8;
                soff = (uint32_t)(((t ? OFF3_AL : OFF3_AH) + row*LDT3 + c16*8) * 2);
            } else {                           // B hi/lo: 2 x 1024 (128 rows x 8)
                int d = c - 4096;
                int t = d >> 10, idx = d & 1023;
                int row = idx >> 3, c16 = idx & 7;
                g = (t ? Wl : Wh) + (size_t)(bn+row)*K + k0 + c16*8;
                soff = (uint32_t)(((t ? OFF3_BL : OFF3_BH) + row*LDT3 + c16*8) * 2);
            }
            cp_async16_sm(base + soff, g);
        }
        asm volatile("cp.async.commit_group;" ::: "memory");
    };

    const int T = K / BK3;
    load_chunk(0, 0);

    for (int i = 0; i < T; i++) {
        const int slot = i & 1;
        asm volatile("cp.async.wait_group 0;" ::: "memory");
        __syncthreads();
        if (i + 1 < T) load_chunk(i + 1, slot ^ 1);

        const bf16* st = sm + slot*STAGE3_HALFS;
        #pragma unroll
        for (int ks = 0; ks < 4; ks++) {
            const int kofs = ks*16;
            AF ah[4], al[4];
            #pragma unroll
            for (int i4 = 0; i4 < 4; i4++) {
                wmma::load_matrix_sync(ah[i4], st + OFF3_AH + (wr*64 + i4*16)*LDT3 + kofs, LDT3);
                wmma::load_matrix_sync(al[i4], st + OFF3_AL + (wr*64 + i4*16)*LDT3 + kofs, LDT3);
            }
            #pragma unroll
            for (int jj = 0; jj < 4; jj++) {
                BFc bh, bl;
                wmma::load_matrix_sync(bh, st + OFF3_BH + (wc*64 + jj*16)*LDT3 + kofs, LDT3);
                wmma::load_matrix_sync(bl, st + OFF3_BL + (wc*64 + jj*16)*LDT3 + kofs, LDT3);
                #pragma unroll
                for (int i4 = 0; i4 < 4; i4++) {
                    wmma::mma_sync(acc[i4][jj], al[i4], bh, acc[i4][jj]);
                    wmma::mma_sync(acc[i4][jj], ah[i4], bl, acc[i4][jj]);
                    wmma::mma_sync(acc[i4][jj], ah[i4], bh, acc[i4][jj]);
                }
            }
        }
    }

    #pragma unroll
    for (int i4 = 0; i4 < 4; i4++)
        #pragma unroll
        for (int jj = 0; jj < 4; jj++) {
            int row = bm + wr*64 + i4*16;
            int col = bn + wc*64 + jj*16;
            wmma::store_matrix_sync(&C[(size_t)row*N + col], acc[i4][jj], N,
                                    wmma::mem_row_major);
        }
}

// ---------------------------------------------------------------------------
// bias + RoPE + transpose; folds (1/sqrt(128))*log2(e) into Q.
// ---------------------------------------------------------------------------
__global__ void __launch_bounds__(256) pack_rope(
    const float* __restrict__ Cqkv,
    const float* __restrict__ bq, const float* __restrict__ bk,
    const float* __restrict__ bv,
    const float* __restrict__ cosp, const float* __restrict__ sinp)
{
    const int token = blockIdx.x;
    const int b = token / SEQ, s = token % SEQ;
    __shared__ float cs[HD], sn[HD];
    if (threadIdx.x < HD) {
        cs[threadIdx.x] = cosp[(size_t)token*HD + threadIdx.x];
        sn[threadIdx.x] = sinp[(size_t)token*HD + threadIdx.x];
    }
    __syncthreads();
    const float scaling = 0.08838834764831845f * 1.4426950408889634f;
    const float* Crow = Cqkv + (size_t)token*NDIMC;

    for (int i = threadIdx.x; i < NH*64; i += blockDim.x) {
        int h = i >> 6, d = i & 63;
        float x1 = Crow[h*HD + d]      + bq[h*HD + d];
        float x2 = Crow[h*HD + d + 64] + bq[h*HD + d + 64];
        float o1 = (x1*cs[d]      - x2*sn[d])      * scaling;
        float o2 = (x2*cs[d + 64] + x1*sn[d + 64]) * scaling;
        size_t ob = ((size_t)(b*NH + h)*SEQ + s)*HD;
        bf16 h1, l1, h2, l2;
        bf16_split(o1, h1, l1);
        bf16_split(o2, h2, l2);
        g_Qh[ob + d] = h1;      g_Ql[ob + d] = l1;
        g_Qh[ob + d + 64] = h2; g_Ql[ob + d + 64] = l2;
    }
    for (int i = threadIdx.x; i < NKV*64; i += blockDim.x) {
        int h = i >> 6, d = i & 63;
        float x1 = Crow[QDIM + h*HD + d]      + bk[h*HD + d];
        float x2 = Crow[QDIM + h*HD + d + 64] + bk[h*HD + d + 64];
        float o1 = x1*cs[d]      - x2*sn[d];
        float o2 = x2*cs[d + 64] + x1*sn[d + 64];
        size_t ob = ((size_t)(b*NKV + h)*SEQ + s)*HD;
        bf16 h1, l1, h2, l2;
        bf16_split(o1, h1, l1);
        bf16_split(o2, h2, l2);
        g_Kh[ob + d] = h1;      g_Kl[ob + d] = l1;
        g_Kh[ob + d + 64] = h2; g_Kl[ob + d + 64] = l2;
    }
    for (int i = threadIdx.x; i < KVDIM; i += blockDim.x) {
        int h = i >> 7, d = i & 127;
        float v = Crow[QDIM + KVDIM + i] + bv[i];
        size_t ob = ((size_t)(b*NKV + h)*SEQ + s)*HD + d;
        bf16 hv, lv;
        bf16_split(v, hv, lv);
        g_Vh[ob] = hv; g_Vl[ob] = lv;
    }
}

// ---------------------------------------------------------------------------
// FlashAttention-2 style causal GQA attention (unchanged from R7)
// ---------------------------------------------------------------------------
#define FBQ 128
#define FBKV 64
#define FLD 136
#define FQT_HALFS (128*FLD)
#define FKV_HALFS (64*FLD)
#define FSTAGE_HALFS (4*FKV_HALFS)
#define FQ_BYTES (2*FQT_HALFS*2)
#define FSTAGE_BYTES (FSTAGE_HALFS*2)
#define FKV_BYTES (FKV_HALFS*2)
#define FATTN_SMEM (FQ_BYTES + 2*FSTAGE_BYTES)

__global__ void __launch_bounds__(256) attn_fa2()
{
    extern __shared__ __align__(16) char smraw[];
    const uint32_t smb = smem_u32(smraw);
    const uint32_t sQh = smb;
    const uint32_t sQl = smb + FQT_HALFS*2;

    const int qt  = blockIdx.x;
    const int h   = blockIdx.y;
    const int b   = blockIdx.z;
    const int kvh = h / NREP;
    const int q0  = qt * FBQ;
    const int tid = threadIdx.x;
    const int warp = tid >> 5;
    const int lane = tid & 31;
    const int R = warp * 16;

    const bf16* Qgh = g_Qh + (size_t)(b*NH  + h  )*SEQ*HD;
    const bf16* Qgl = g_Ql + (size_t)(b*NH  + h  )*SEQ*HD;
    const bf16* Kgh = g_Kh + (size_t)(b*NKV + kvh)*SEQ*HD;
    const bf16* Kgl = g_Kl + (size_t)(b*NKV + kvh)*SEQ*HD;
    const bf16* Vgh = g_Vh + (size_t)(b*NKV + kvh)*SEQ*HD;
    const bf16* Vgl = g_Vl + (size_t)(b*NKV + kvh)*SEQ*HD;

    {
        bf16* qsm = (bf16*)smraw;
        #pragma unroll
        for (int it = 0; it < 16; it++) {
            int c = tid + it*256;
            int t = c >> 11, idx = c & 2047;
            int row = idx >> 4, c16 = idx & 15;
            const bf16* src = (t ? Qgl : Qgh) + (size_t)(q0+row)*HD + c16*8;
            *(uint4*)(qsm + t*FQT_HALFS + row*FLD + c16*8) = *(const uint4*)src;
        }
    }

    auto load_kv = [&](int j, int s) {
        const uint32_t base = smb + FQ_BYTES + (uint32_t)(s*FSTAGE_BYTES);
        #pragma unroll
        for (int it = 0; it < 16; it++) {
            int c = tid + it*256;
            int t = c >> 10, idx = c & 1023;
            int row = idx >> 4, c16 = idx & 15;
            const bf16* src;
            if      (t == 0) src = Kgh;
            else if (t == 1) src = Kgl;
            else if (t == 2) src = Vgh;
            else             src = Vgl;
            cp_async16_sm(base + (uint32_t)((t*FKV_HALFS + row*FLD + c16*8)*2),
                          src + (size_t)(j*FBKV+row)*HD + c16*8);
        }
        asm volatile("cp.async.commit_group;" ::: "memory");
    };

    const int nt = 2*qt + 2;
    load_kv(0, 0);
    __syncthreads();

    float oc[16][4];
    #pragma unroll
    for (int i = 0; i < 16; i++)
        #pragma unroll
        for (int c = 0; c < 4; c++) oc[i][c] = 0.f;
    float m_lo = -INFINITY, m_hi = -INFINITY;
    float l_lo = 0.f, l_hi = 0.f;

    const int row_lo = q0 + R + (lane >> 2);
    const int row_hi = row_lo + 8;

    for (int j = 0; j < nt; j++) {
        const int s = j & 1;
        asm volatile("cp.async.wait_group 0;" ::: "memory");
        __syncthreads();
        if (j + 1 < nt) load_kv(j + 1, s ^ 1);

        if (j*FBKV > q0 + R + 15) continue;

        const uint32_t stg = smb + FQ_BYTES + (uint32_t)(s*FSTAGE_BYTES);
        const uint32_t sKh = stg;
        const uint32_t sKl = stg + FKV_BYTES;
        const uint32_t sVh = stg + 2*FKV_BYTES;
        const uint32_t sVl = stg + 3*FKV_BYTES;

        float sc[8][4];
        #pragma unroll
        for (int nb = 0; nb < 8; nb++)
            #pragma unroll
            for (int c = 0; c < 4; c++) sc[nb][c] = 0.f;

        #pragma unroll
        for (int ks = 0; ks < 8; ks++) {
            uint32_t qh[4], ql[4];
            int qrow = R + (lane & 7) + ((lane >> 3) & 1)*8;
            int qcol = ks*16 + ((lane >> 4) & 1)*8;
            ldsm_x4(qh, sQh + (uint32_t)((qrow*FLD + qcol)*2));
            ldsm_x4(ql, sQl + (uint32_t)((qrow*FLD + qcol)*2));
            #pragma unroll
            for (int nb = 0; nb < 8; nb++) {
                uint32_t kh[2], kl[2];
                int krow = nb*8 + (lane & 7);
                int kcol = ks*16 + ((lane >> 3) & 1)*8;
                ldsm_x2(kh, sKh + (uint32_t)((krow*FLD + kcol)*2));
                ldsm_x2(kl, sKl + (uint32_t)((krow*FLD + kcol)*2));
                mma16816(sc[nb], ql, kh);
                mma16816(sc[nb], qh, kl);
                mma16816(sc[nb], qh, kh);
            }
        }

        const bool masked = (j*FBKV + 63 > q0 + R);
        const int cb = j*FBKV + (lane & 3)*2;
        float tmlo = -INFINITY, tmhi = -INFINITY;
        if (!masked) {
            #pragma unroll
            for (int nb = 0; nb < 8; nb++) {
                tmlo = fmaxf(tmlo, fmaxf(sc[nb][0], sc[nb][1]));
                tmhi = fmaxf(tmhi, fmaxf(sc[nb][2], sc[nb][3]));
            }
        } else {
            #pragma unroll
            for (int nb = 0; nb < 8; nb++) {
                int c0 = cb + nb*8, c1 = c0 + 1;
                if (c0 <= row_lo) tmlo = fmaxf(tmlo, sc[nb][0]);
                if (c1 <= row_lo) tmlo = fmaxf(tmlo, sc[nb][1]);
                if (c0 <= row_hi) tmhi = fmaxf(tmhi, sc[nb][2]);
                if (c1 <= row_hi) tmhi = fmaxf(tmhi, sc[nb][3]);
            }
        }
        tmlo = fmaxf(tmlo, __shfl_xor_sync(0xffffffffu, tmlo, 1));
        tmlo = fmaxf(tmlo, __shfl_xor_sync(0xffffffffu, tmlo, 2));
        tmhi = fmaxf(tmhi, __shfl_xor_sync(0xffffffffu, tmhi, 1));
        tmhi = fmaxf(tmhi, __shfl_xor_sync(0xffffffffu, tmhi, 2));

        float mn_lo = fmaxf(m_lo, tmlo);
        float mn_hi = fmaxf(m_hi, tmhi);
        float alpha_lo = exp2f(m_lo - mn_lo);
        float alpha_hi = exp2f(m_hi - mn_hi);
        m_lo = mn_lo; m_hi = mn_hi;
        #pragma unroll
        for (int nb = 0; nb < 16; nb++) {
            oc[nb][0] *= alpha_lo; oc[nb][1] *= alpha_lo;
            oc[nb][2] *= alpha_hi; oc[nb][3] *= alpha_hi;
        }

        float slo = 0.f, shi = 0.f;
        #pragma unroll
        for (int nb = 0; nb < 8; nb++) {
            float p0 = exp2f(sc[nb][0] - mn_lo);
            float p1 = exp2f(sc[nb][1] - mn_lo);
            float p2 = exp2f(sc[nb][2] - mn_hi);
            float p3 = exp2f(sc[nb][3] - mn_hi);
            if (masked) {
                int c0 = cb + nb*8, c1 = c0 + 1;
                if (c0 > row_lo) p0 = 0.f;
                if (c1 > row_lo) p1 = 0.f;
                if (c0 > row_hi) p2 = 0.f;
                if (c1 > row_hi) p3 = 0.f;
            }
            sc[nb][0] = p0; sc[nb][1] = p1; sc[nb][2] = p2; sc[nb][3] = p3;
            slo += p0 + p1; shi += p2 + p3;
        }
        slo += __shfl_xor_sync(0xffffffffu, slo, 1);
        slo += __shfl_xor_sync(0xffffffffu, slo, 2);
        shi += __shfl_xor_sync(0xffffffffu, shi, 1);
        shi += __shfl_xor_sync(0xffffffffu, shi, 2);
        l_lo = l_lo * alpha_lo + slo;
        l_hi = l_hi * alpha_hi + shi;

        #pragma unroll
        for (int ks2 = 0; ks2 < 4; ks2++) {
            uint32_t pah[4], pal[4];
            #pragma unroll
            for (int half = 0; half < 2; half++) {
                const float* f = sc[2*ks2 + half];
                bf16 h0, l0, h1, l1, h2, l2, h3, l3;
                bf16_split(f[0], h0, l0);
                bf16_split(f[1], h1, l1);
                bf16_split(f[2], h2, l2);
                bf16_split(f[3], h3, l3);
                pah[half*2 + 0] = pack_bf2(__bfloat162float(h0), __bfloat162float(h1));
                pah[half*2 + 1] = pack_bf2(__bfloat162float(h2), __bfloat162float(h3));
                pal[half*2 + 0] = pack_bf2(__bfloat162float(l0), __bfloat162float(l1));
                pal[half*2 + 1] = pack_bf2(__bfloat162float(l2), __bfloat162float(l3));
            }
            #pragma unroll
            for (int nb = 0; nb < 16; nb++) {
                uint32_t vh[2], vl[2];
                int vrow = ks2*16 + (lane & 7) + ((lane >> 3) & 1)*8;
                int vcol = nb*8;
                ldsm_x2t(vh, sVh + (uint32_t)((vrow*FLD + vcol)*2));
                ldsm_x2t(vl, sVl + (uint32_t)((vrow*FLD + vcol)*2));
                mma16816(oc[nb], pal, vh);
                mma16816(oc[nb], pah, vl);
                mma16816(oc[nb], pah, vh);
            }
        }
    }

    {
        float inv_lo = 1.f / l_lo;
        float inv_hi = 1.f / l_hi;
        size_t base_lo = ((size_t)(b*SEQ + row_lo))*QDIM + h*HD;
        size_t base_hi = ((size_t)(b*SEQ + row_hi))*QDIM + h*HD;
        #pragma unroll
        for (int nb = 0; nb < 16; nb++) {
            int n0 = nb*8 + (lane & 3)*2;
            float f0 = oc[nb][0]*inv_lo, f1 = oc[nb][1]*inv_lo;
            float f2 = oc[nb][2]*inv_hi, f3 = oc[nb][3]*inv_hi;
            bf16 h0, l0, h1, l1, h2, l2, h3, l3;
            bf16_split(f0, h0, l0);
            bf16_split(f1, h1, l1);
            bf16_split(f2, h2, l2);
            bf16_split(f3, h3, l3);
            *(uint32_t*)&g_Ah[base_lo + n0] = pack_bf2(__bfloat162float(h0), __bfloat162float(h1));
            *(uint32_t*)&g_Al[base_lo + n0] = pack_bf2(__bfloat162float(l0), __bfloat162float(l1));
            *(uint32_t*)&g_Ah[base_hi + n0] = pack_bf2(__bfloat162float(h2), __bfloat162float(h3));
            *(uint32_t*)&g_Al[base_hi + n0] = pack_bf2(__bfloat162float(l2), __bfloat162float(l3));
        }
    }
}

// ---------------------------------------------------------------------------
// launch
// ---------------------------------------------------------------------------
extern "C" void kernel_launch(void* const* d_in, const int* in_sizes, int n_in,
                              void* d_out, int out_size)
{
    (void)in_sizes; (void)n_in; (void)out_size;
    const float* hs   = (const float*)d_in[0];
    const float* cosp = (const float*)d_in[1];
    const float* sinp = (const float*)d_in[2];
    const float* Wq   = (const float*)d_in[3];
    const float* bq   = (const float*)d_in[4];
    const float* Wk   = (const float*)d_in[5];
    const float* bk   = (const float*)d_in[6];
    const float* Wv   = (const float*)d_in[7];
    const float* bv   = (const float*)d_in[8];
    const float* Wo   = (const float*)d_in[9];
    float* out = (float*)d_out;

    float *Cqkv;
    bf16 *hsh, *hsl, *Wch, *Wcl, *Woh, *Wol, *Ah, *Al;
    cudaGetSymbolAddress((void**)&Cqkv, g_Cqkv);
    cudaGetSymbolAddress((void**)&hsh, g_hsh);
    cudaGetSymbolAddress((void**)&hsl, g_hsl);
    cudaGetSymbolAddress((void**)&Wch, g_Wch);
    cudaGetSymbolAddress((void**)&Wcl, g_Wcl);
    cudaGetSymbolAddress((void**)&Woh, g_Woh);
    cudaGetSymbolAddress((void**)&Wol, g_Wol);
    cudaGetSymbolAddress((void**)&Ah,  g_Ah);
    cudaGetSymbolAddress((void**)&Al,  g_Al);

    cudaFuncSetAttribute(gemm_v3,
                         cudaFuncAttributeMaxDynamicSharedMemorySize,
                         SMEM3_BYTES);
    cudaFuncSetAttribute(attn_fa2,
                         cudaFuncAttributeMaxDynamicSharedMemorySize,
                         FATTN_SMEM);

    auto split = [&](const float* src, bf16* hi, bf16* lo, size_t n) {
        size_t n4 = n / 4;
        split_bf16<<<(unsigned)((n4 + 255)/256), 256>>>(
            (const float4*)src, (__nv_bfloat162*)hi, (__nv_bfloat162*)lo, n4);
    };
    split(hs, hsh, hsl, (size_t)M_TOK*HIDDEN);
    split(Wq, Wch,                               Wcl,                               (size_t)QDIM*HIDDEN);
    split(Wk, Wch + (size_t)QDIM*HIDDEN,         Wcl + (size_t)QDIM*HIDDEN,         (size_t)KVDIM*HIDDEN);
    split(Wv, Wch + (size_t)(QDIM+KVDIM)*HIDDEN, Wcl + (size_t)(QDIM+KVDIM)*HIDDEN, (size_t)KVDIM*HIDDEN);
    split(Wo, Woh, Wol, (size_t)HIDDEN*QDIM);

    gemm_v3<<<dim3(NDIMC/BN3, M_TOK/BM3), 256, SMEM3_BYTES>>>(
        hsh, hsl, Wch, Wcl, Cqkv, M_TOK, NDIMC, HIDDEN);
    pack_rope<<<M_TOK, 256>>>(Cqkv, bq, bk, bv, cosp, sinp);
    attn_fa2<<<dim3(SEQ/FBQ, NH, BATCH), 256, FATTN_SMEM>>>();
    gemm_v3<<<dim3(QDIM/BN3, M_TOK/BM3), 256, SMEM3_BYTES>>>(
        Ah, Al, Woh, Wol, out, M_TOK, QDIM, HIDDEN);
}

// round 9
// speedup vs baseline: 5.3197x; 1.0619x over previous
#include <cuda_runtime.h>
#include <cuda_bf16.h>
#include <mma.h>
#include <math.h>
#include <cstdint>
#include <cstddef>

#define HIDDEN 3584
#define NH 28
#define NKV 4
#define HD 128
#define NREP 7
#define BATCH 2
#define SEQ 2048
#define M_TOK (BATCH*SEQ)   // 4096
#define QDIM (NH*HD)        // 3584
#define KVDIM (NKV*HD)      // 512
#define NDIMC (QDIM + 2*KVDIM)   // 4608

typedef __nv_bfloat16 bf16;

// ---------------------------------------------------------------------------
// Scratch
// ---------------------------------------------------------------------------
__device__ float g_Cqkv[(size_t)M_TOK*NDIMC];

__device__ __align__(128) bf16 g_hsh[(size_t)M_TOK*HIDDEN];
__device__ __align__(128) bf16 g_hsl[(size_t)M_TOK*HIDDEN];
__device__ __align__(128) bf16 g_Wch[(size_t)NDIMC*HIDDEN];
__device__ __align__(128) bf16 g_Wcl[(size_t)NDIMC*HIDDEN];
__device__ __align__(128) bf16 g_Woh[(size_t)HIDDEN*QDIM];
__device__ __align__(128) bf16 g_Wol[(size_t)HIDDEN*QDIM];

__device__ __align__(128) bf16 g_Qh[(size_t)M_TOK*QDIM];   // [B][NH][S][D]
__device__ __align__(128) bf16 g_Ql[(size_t)M_TOK*QDIM];
__device__ __align__(128) bf16 g_Kh[(size_t)M_TOK*KVDIM];  // [B][NKV][S][D]
__device__ __align__(128) bf16 g_Kl[(size_t)M_TOK*KVDIM];
__device__ __align__(128) bf16 g_Vh[(size_t)M_TOK*KVDIM];
__device__ __align__(128) bf16 g_Vl[(size_t)M_TOK*KVDIM];
__device__ __align__(128) bf16 g_Ah[(size_t)M_TOK*QDIM];
__device__ __align__(128) bf16 g_Al[(size_t)M_TOK*QDIM];

// ---------------------------------------------------------------------------
// helpers
// ---------------------------------------------------------------------------
__device__ __forceinline__ void bf16_split(float x, bf16& hi, bf16& lo) {
    hi = __float2bfloat16(x);
    lo = __float2bfloat16(x - __bfloat162float(hi));
}
__device__ __forceinline__ uint32_t smem_u32(const void* p) {
    return (uint32_t)__cvta_generic_to_shared(p);
}
__device__ __forceinline__ void cp_async16_sm(uint32_t s, const void* g) {
    asm volatile("cp.async.cg.shared.global [%0], [%1], 16;\n"
                 :: "r"(s), "l"(g));
}
__device__ __forceinline__ void ldsm_x4(uint32_t r[4], uint32_t addr) {
    asm volatile("ldmatrix.sync.aligned.m8n8.x4.shared.b16 {%0,%1,%2,%3}, [%4];"
        : "=r"(r[0]), "=r"(r[1]), "=r"(r[2]), "=r"(r[3]) : "r"(addr));
}
__device__ __forceinline__ void ldsm_x2(uint32_t r[2], uint32_t addr) {
    asm volatile("ldmatrix.sync.aligned.m8n8.x2.shared.b16 {%0,%1}, [%2];"
        : "=r"(r[0]), "=r"(r[1]) : "r"(addr));
}
__device__ __forceinline__ void ldsm_x2t(uint32_t r[2], uint32_t addr) {
    asm volatile("ldmatrix.sync.aligned.m8n8.x2.trans.shared.b16 {%0,%1}, [%2];"
        : "=r"(r[0]), "=r"(r[1]) : "r"(addr));
}
__device__ __forceinline__ void mma16816(float d[4], const uint32_t a[4],
                                         const uint32_t b[2]) {
    asm volatile(
        "mma.sync.aligned.m16n8k16.row.col.f32.bf16.bf16.f32 "
        "{%0,%1,%2,%3}, {%4,%5,%6,%7}, {%8,%9}, {%0,%1,%2,%3};"
        : "+f"(d[0]), "+f"(d[1]), "+f"(d[2]), "+f"(d[3])
        : "r"(a[0]), "r"(a[1]), "r"(a[2]), "r"(a[3]), "r"(b[0]), "r"(b[1]));
}
__device__ __forceinline__ uint32_t pack_bf2(float lo, float hi) {
    __nv_bfloat162 v(__float2bfloat16(lo), __float2bfloat16(hi));
    return *(uint32_t*)&v;
}

// elementwise split fp32 -> bf16 hi/lo
__global__ void __launch_bounds__(256) split_bf16(
    const float4* __restrict__ src, __nv_bfloat162* __restrict__ hi,
    __nv_bfloat162* __restrict__ lo, size_t n4)
{
    size_t i = (size_t)blockIdx.x*blockDim.x + threadIdx.x;
    if (i >= n4) return;
    float4 v = src[i];
    bf16 hx, lx, hy, ly, hz, lz, hw, lw;
    bf16_split(v.x, hx, lx);
    bf16_split(v.y, hy, ly);
    bf16_split(v.z, hz, lz);
    bf16_split(v.w, hw, lw);
    hi[2*i]   = __nv_bfloat162(hx, hy);
    hi[2*i+1] = __nv_bfloat162(hz, hw);
    lo[2*i]   = __nv_bfloat162(lx, ly);
    lo[2*i+1] = __nv_bfloat162(lz, lw);
}

// ---------------------------------------------------------------------------
// 3xBF16 GEMM v4: raw ldsm/mma.sync with software-pipelined B fragments.
// BM=256 BN=128 BK=64, 2-stage cp.async, 8 warps, warp tile 64x64.
// ---------------------------------------------------------------------------
#define BM3 256
#define BN3 128
#define BK3 64
#define LDT3 72
#define OFF3_AH 0
#define OFF3_AL (BM3*LDT3)
#define OFF3_BH (2*BM3*LDT3)
#define OFF3_BL (2*BM3*LDT3 + BN3*LDT3)
#define STAGE3_HALFS (2*BM3*LDT3 + 2*BN3*LDT3)   // 55296
#define SMEM3_BYTES (2*STAGE3_HALFS*2)           // 221184

__global__ void __launch_bounds__(256,1) gemm_v4(
    const bf16* __restrict__ Ah, const bf16* __restrict__ Al,
    const bf16* __restrict__ Wh, const bf16* __restrict__ Wl,
    float* __restrict__ C, int M, int N, int K)
{
    extern __shared__ __align__(16) bf16 sm[];
    const uint32_t smb = smem_u32(sm);
    const int tid  = threadIdx.x;
    const int warp = tid >> 5;
    const int lane = tid & 31;
    const int wr   = warp >> 1;        // 0..3 : 64-row band
    const int wc   = warp & 1;         // 0..1 : 64-col band
    const int bm   = blockIdx.y * BM3;
    const int bn   = blockIdx.x * BN3;

    float acc[4][8][4];
    #pragma unroll
    for (int mi = 0; mi < 4; mi++)
        #pragma unroll
        for (int nb = 0; nb < 8; nb++)
            #pragma unroll
            for (int c = 0; c < 4; c++) acc[mi][nb][c] = 0.f;

    auto load_chunk = [&](int chunk, int slot) {
        const int k0 = chunk * BK3;
        const uint32_t base = smb + (uint32_t)(slot*STAGE3_HALFS*2);
        #pragma unroll
        for (int it = 0; it < 24; it++) {
            int c = tid + it*256;
            const bf16* g;
            uint32_t soff;
            if (c < 4096) {
                int t = c >> 11, idx = c & 2047;
                int row = idx >> 3, c16 = idx & 7;
                g = (t ? Al : Ah) + (size_t)(bm+row)*K + k0 + c16*8;
                soff = (uint32_t)(((t ? OFF3_AL : OFF3_AH) + row*LDT3 + c16*8) * 2);
            } else {
                int d = c - 4096;
                int t = d >> 10, idx = d & 1023;
                int row = idx >> 3, c16 = idx & 7;
                g = (t ? Wl : Wh) + (size_t)(bn+row)*K + k0 + c16*8;
                soff = (uint32_t)(((t ? OFF3_BL : OFF3_BH) + row*LDT3 + c16*8) * 2);
            }
            cp_async16_sm(base + soff, g);
        }
        asm volatile("cp.async.commit_group;" ::: "memory");
    };

    // ldsm addressing (per-lane), same scheme validated in the attention kernel
    const int arow = wr*64 + (lane & 7) + ((lane >> 3) & 1)*8;   // + mi*16
    const int acol8 = ((lane >> 4) & 1)*8;
    const int brow = wc*64 + (lane & 7);                          // + nb*8
    const int bcol8 = ((lane >> 3) & 1)*8;

    const int T = K / BK3;
    load_chunk(0, 0);

    for (int i = 0; i < T; i++) {
        const int slot = i & 1;
        asm volatile("cp.async.wait_group 0;" ::: "memory");
        __syncthreads();
        if (i + 1 < T) load_chunk(i + 1, slot ^ 1);

        const uint32_t st = smb + (uint32_t)(slot*STAGE3_HALFS*2);
        const uint32_t sAh = st + OFF3_AH*2;
        const uint32_t sAl = st + OFF3_AL*2;
        const uint32_t sBh = st + OFF3_BH*2;
        const uint32_t sBl = st + OFF3_BL*2;

        #pragma unroll
        for (int ks = 0; ks < 4; ks++) {
            const int kofs = ks*16;
            uint32_t ah[4][4], al[4][4];
            #pragma unroll
            for (int mi = 0; mi < 4; mi++) {
                uint32_t ao = (uint32_t)(((arow + mi*16)*LDT3 + kofs + acol8)*2);
                ldsm_x4(ah[mi], sAh + ao);
                ldsm_x4(al[mi], sAl + ao);
            }
            // software-pipelined B: load nb+1 while computing nb
            uint32_t bh[2][2], bl[2][2];
            {
                uint32_t bo = (uint32_t)((brow*LDT3 + kofs + bcol8)*2);
                ldsm_x2(bh[0], sBh + bo);
                ldsm_x2(bl[0], sBl + bo);
            }
            #pragma unroll
            for (int nb = 0; nb < 8; nb++) {
                const int cur = nb & 1;
                if (nb < 7) {
                    uint32_t bo = (uint32_t)(((brow + (nb+1)*8)*LDT3 + kofs + bcol8)*2);
                    ldsm_x2(bh[cur ^ 1], sBh + bo);
                    ldsm_x2(bl[cur ^ 1], sBl + bo);
                }
                #pragma unroll
                for (int mi = 0; mi < 4; mi++) {
                    mma16816(acc[mi][nb], al[mi], bh[cur]);
                    mma16816(acc[mi][nb], ah[mi], bl[cur]);
                    mma16816(acc[mi][nb], ah[mi], bh[cur]);
                }
            }
        }
    }

    // epilogue: direct float2 stores from accumulator fragments
    {
        const int r0 = bm + wr*64 + (lane >> 2);
        const int c0 = bn + wc*64 + (lane & 3)*2;
        #pragma unroll
        for (int mi = 0; mi < 4; mi++)
            #pragma unroll
            for (int nb = 0; nb < 8; nb++) {
                float* p0 = &C[(size_t)(r0 + mi*16)*N + c0 + nb*8];
                float* p1 = &C[(size_t)(r0 + mi*16 + 8)*N + c0 + nb*8];
                *(float2*)p0 = make_float2(acc[mi][nb][0], acc[mi][nb][1]);
                *(float2*)p1 = make_float2(acc[mi][nb][2], acc[mi][nb][3]);
            }
    }
}

// ---------------------------------------------------------------------------
// bias + RoPE + transpose; folds (1/sqrt(128))*log2(e) into Q.
// ---------------------------------------------------------------------------
__global__ void __launch_bounds__(256) pack_rope(
    const float* __restrict__ Cqkv,
    const float* __restrict__ bq, const float* __restrict__ bk,
    const float* __restrict__ bv,
    const float* __restrict__ cosp, const float* __restrict__ sinp)
{
    const int token = blockIdx.x;
    const int b = token / SEQ, s = token % SEQ;
    __shared__ float cs[HD], sn[HD];
    if (threadIdx.x < HD) {
        cs[threadIdx.x] = cosp[(size_t)token*HD + threadIdx.x];
        sn[threadIdx.x] = sinp[(size_t)token*HD + threadIdx.x];
    }
    __syncthreads();
    const float scaling = 0.08838834764831845f * 1.4426950408889634f;
    const float* Crow = Cqkv + (size_t)token*NDIMC;

    for (int i = threadIdx.x; i < NH*64; i += blockDim.x) {
        int h = i >> 6, d = i & 63;
        float x1 = Crow[h*HD + d]      + bq[h*HD + d];
        float x2 = Crow[h*HD + d + 64] + bq[h*HD + d + 64];
        float o1 = (x1*cs[d]      - x2*sn[d])      * scaling;
        float o2 = (x2*cs[d + 64] + x1*sn[d + 64]) * scaling;
        size_t ob = ((size_t)(b*NH + h)*SEQ + s)*HD;
        bf16 h1, l1, h2, l2;
        bf16_split(o1, h1, l1);
        bf16_split(o2, h2, l2);
        g_Qh[ob + d] = h1;      g_Ql[ob + d] = l1;
        g_Qh[ob + d + 64] = h2; g_Ql[ob + d + 64] = l2;
    }
    for (int i = threadIdx.x; i < NKV*64; i += blockDim.x) {
        int h = i >> 6, d = i & 63;
        float x1 = Crow[QDIM + h*HD + d]      + bk[h*HD + d];
        float x2 = Crow[QDIM + h*HD + d + 64] + bk[h*HD + d + 64];
        float o1 = x1*cs[d]      - x2*sn[d];
        float o2 = x2*cs[d + 64] + x1*sn[d + 64];
        size_t ob = ((size_t)(b*NKV + h)*SEQ + s)*HD;
        bf16 h1, l1, h2, l2;
        bf16_split(o1, h1, l1);
        bf16_split(o2, h2, l2);
        g_Kh[ob + d] = h1;      g_Kl[ob + d] = l1;
        g_Kh[ob + d + 64] = h2; g_Kl[ob + d + 64] = l2;
    }
    for (int i = threadIdx.x; i < KVDIM; i += blockDim.x) {
        int h = i >> 7, d = i & 127;
        float v = Crow[QDIM + KVDIM + i] + bv[i];
        size_t ob = ((size_t)(b*NKV + h)*SEQ + s)*HD + d;
        bf16 hv, lv;
        bf16_split(v, hv, lv);
        g_Vh[ob] = hv; g_Vl[ob] = lv;
    }
}

// ---------------------------------------------------------------------------
// FlashAttention-2 causal GQA attention (heavy-tiles-first scheduling)
// ---------------------------------------------------------------------------
#define FBQ 128
#define FBKV 64
#define FLD 136
#define FQT_HALFS (128*FLD)
#define FKV_HALFS (64*FLD)
#define FSTAGE_HALFS (4*FKV_HALFS)
#define FQ_BYTES (2*FQT_HALFS*2)
#define FSTAGE_BYTES (FSTAGE_HALFS*2)
#define FKV_BYTES (FKV_HALFS*2)
#define FATTN_SMEM (FQ_BYTES + 2*FSTAGE_BYTES)
#define NQT (SEQ/FBQ)

__global__ void __launch_bounds__(256) attn_fa2()
{
    extern __shared__ __align__(16) char smraw[];
    const uint32_t smb = smem_u32(smraw);
    const uint32_t sQh = smb;
    const uint32_t sQl = smb + FQT_HALFS*2;

    const int qt  = (NQT - 1) - blockIdx.x;   // heavy tiles launch first
    const int h   = blockIdx.y;
    const int b   = blockIdx.z;
    const int kvh = h / NREP;
    const int q0  = qt * FBQ;
    const int tid = threadIdx.x;
    const int warp = tid >> 5;
    const int lane = tid & 31;
    const int R = warp * 16;

    const bf16* Qgh = g_Qh + (size_t)(b*NH  + h  )*SEQ*HD;
    const bf16* Qgl = g_Ql + (size_t)(b*NH  + h  )*SEQ*HD;
    const bf16* Kgh = g_Kh + (size_t)(b*NKV + kvh)*SEQ*HD;
    const bf16* Kgl = g_Kl + (size_t)(b*NKV + kvh)*SEQ*HD;
    const bf16* Vgh = g_Vh + (size_t)(b*NKV + kvh)*SEQ*HD;
    const bf16* Vgl = g_Vl + (size_t)(b*NKV + kvh)*SEQ*HD;

    {
        bf16* qsm = (bf16*)smraw;
        #pragma unroll
        for (int it = 0; it < 16; it++) {
            int c = tid + it*256;
            int t = c >> 11, idx = c & 2047;
            int row = idx >> 4, c16 = idx & 15;
            const bf16* src = (t ? Qgl : Qgh) + (size_t)(q0+row)*HD + c16*8;
            *(uint4*)(qsm + t*FQT_HALFS + row*FLD + c16*8) = *(const uint4*)src;
        }
    }

    auto load_kv = [&](int j, int s) {
        const uint32_t base = smb + FQ_BYTES + (uint32_t)(s*FSTAGE_BYTES);
        #pragma unroll
        for (int it = 0; it < 16; it++) {
            int c = tid + it*256;
            int t = c >> 10, idx = c & 1023;
            int row = idx >> 4, c16 = idx & 15;
            const bf16* src;
            if      (t == 0) src = Kgh;
            else if (t == 1) src = Kgl;
            else if (t == 2) src = Vgh;
            else             src = Vgl;
            cp_async16_sm(base + (uint32_t)((t*FKV_HALFS + row*FLD + c16*8)*2),
                          src + (size_t)(j*FBKV+row)*HD + c16*8);
        }
        asm volatile("cp.async.commit_group;" ::: "memory");
    };

    const int nt = 2*qt + 2;
    load_kv(0, 0);
    __syncthreads();

    float oc[16][4];
    #pragma unroll
    for (int i = 0; i < 16; i++)
        #pragma unroll
        for (int c = 0; c < 4; c++) oc[i][c] = 0.f;
    float m_lo = -INFINITY, m_hi = -INFINITY;
    float l_lo = 0.f, l_hi = 0.f;

    const int row_lo = q0 + R + (lane >> 2);
    const int row_hi = row_lo + 8;

    for (int j = 0; j < nt; j++) {
        const int s = j & 1;
        asm volatile("cp.async.wait_group 0;" ::: "memory");
        __syncthreads();
        if (j + 1 < nt) load_kv(j + 1, s ^ 1);

        if (j*FBKV > q0 + R + 15) continue;

        const uint32_t stg = smb + FQ_BYTES + (uint32_t)(s*FSTAGE_BYTES);
        const uint32_t sKh = stg;
        const uint32_t sKl = stg + FKV_BYTES;
        const uint32_t sVh = stg + 2*FKV_BYTES;
        const uint32_t sVl = stg + 3*FKV_BYTES;

        float sc[8][4];
        #pragma unroll
        for (int nb = 0; nb < 8; nb++)
            #pragma unroll
            for (int c = 0; c < 4; c++) sc[nb][c] = 0.f;

        #pragma unroll
        for (int ks = 0; ks < 8; ks++) {
            uint32_t qh[4], ql[4];
            int qrow = R + (lane & 7) + ((lane >> 3) & 1)*8;
            int qcol = ks*16 + ((lane >> 4) & 1)*8;
            ldsm_x4(qh, sQh + (uint32_t)((qrow*FLD + qcol)*2));
            ldsm_x4(ql, sQl + (uint32_t)((qrow*FLD + qcol)*2));
            #pragma unroll
            for (int nb = 0; nb < 8; nb++) {
                uint32_t kh[2], kl[2];
                int krow = nb*8 + (lane & 7);
                int kcol = ks*16 + ((lane >> 3) & 1)*8;
                ldsm_x2(kh, sKh + (uint32_t)((krow*FLD + kcol)*2));
                ldsm_x2(kl, sKl + (uint32_t)((krow*FLD + kcol)*2));
                mma16816(sc[nb], ql, kh);
                mma16816(sc[nb], qh, kl);
                mma16816(sc[nb], qh, kh);
            }
        }

        const bool masked = (j*FBKV + 63 > q0 + R);
        const int cb = j*FBKV + (lane & 3)*2;
        float tmlo = -INFINITY, tmhi = -INFINITY;
        if (!masked) {
            #pragma unroll
            for (int nb = 0; nb < 8; nb++) {
                tmlo = fmaxf(tmlo, fmaxf(sc[nb][0], sc[nb][1]));
                tmhi = fmaxf(tmhi, fmaxf(sc[nb][2], sc[nb][3]));
            }
        } else {
            #pragma unroll
            for (int nb = 0; nb < 8; nb++) {
                int c0 = cb + nb*8, c1 = c0 + 1;
                if (c0 <= row_lo) tmlo = fmaxf(tmlo, sc[nb][0]);
                if (c1 <= row_lo) tmlo = fmaxf(tmlo, sc[nb][1]);
                if (c0 <= row_hi) tmhi = fmaxf(tmhi, sc[nb][2]);
                if (c1 <= row_hi) tmhi = fmaxf(tmhi, sc[nb][3]);
            }
        }
        tmlo = fmaxf(tmlo, __shfl_xor_sync(0xffffffffu, tmlo, 1));
        tmlo = fmaxf(tmlo, __shfl_xor_sync(0xffffffffu, tmlo, 2));
        tmhi = fmaxf(tmhi, __shfl_xor_sync(0xffffffffu, tmhi, 1));
        tmhi = fmaxf(tmhi, __shfl_xor_sync(0xffffffffu, tmhi, 2));

        float mn_lo = fmaxf(m_lo, tmlo);
        float mn_hi = fmaxf(m_hi, tmhi);
        float alpha_lo = exp2f(m_lo - mn_lo);
        float alpha_hi = exp2f(m_hi - mn_hi);
        m_lo = mn_lo; m_hi = mn_hi;
        #pragma unroll
        for (int nb = 0; nb < 16; nb++) {
            oc[nb][0] *= alpha_lo; oc[nb][1] *= alpha_lo;
            oc[nb][2] *= alpha_hi; oc[nb][3] *= alpha_hi;
        }

        float slo = 0.f, shi = 0.f;
        #pragma unroll
        for (int nb = 0; nb < 8; nb++) {
            float p0 = exp2f(sc[nb][0] - mn_lo);
            float p1 = exp2f(sc[nb][1] - mn_lo);
            float p2 = exp2f(sc[nb][2] - mn_hi);
            float p3 = exp2f(sc[nb][3] - mn_hi);
            if (masked) {
                int c0 = cb + nb*8, c1 = c0 + 1;
                if (c0 > row_lo) p0 = 0.f;
                if (c1 > row_lo) p1 = 0.f;
                if (c0 > row_hi) p2 = 0.f;
                if (c1 > row_hi) p3 = 0.f;
            }
            sc[nb][0] = p0; sc[nb][1] = p1; sc[nb][2] = p2; sc[nb][3] = p3;
            slo += p0 + p1; shi += p2 + p3;
        }
        slo += __shfl_xor_sync(0xffffffffu, slo, 1);
        slo += __shfl_xor_sync(0xffffffffu, slo, 2);
        shi += __shfl_xor_sync(0xffffffffu, shi, 1);
        shi += __shfl_xor_sync(0xffffffffu, shi, 2);
        l_lo = l_lo * alpha_lo + slo;
        l_hi = l_hi * alpha_hi + shi;

        #pragma unroll
        for (int ks2 = 0; ks2 < 4; ks2++) {
            uint32_t pah[4], pal[4];
            #pragma unroll
            for (int half = 0; half < 2; half++) {
                const float* f = sc[2*ks2 + half];
                bf16 h0, l0, h1, l1, h2, l2, h3, l3;
                bf16_split(f[0], h0, l0);
                bf16_split(f[1], h1, l1);
                bf16_split(f[2], h2, l2);
                bf16_split(f[3], h3, l3);
                pah[half*2 + 0] = pack_bf2(__bfloat162float(h0), __bfloat162float(h1));
                pah[half*2 + 1] = pack_bf2(__bfloat162float(h2), __bfloat162float(h3));
                pal[half*2 + 0] = pack_bf2(__bfloat162float(l0), __bfloat162float(l1));
                pal[half*2 + 1] = pack_bf2(__bfloat162float(l2), __bfloat162float(l3));
            }
            #pragma unroll
            for (int nb = 0; nb < 16; nb++) {
                uint32_t vh[2], vl[2];
                int vrow = ks2*16 + (lane & 7) + ((lane >> 3) & 1)*8;
                int vcol = nb*8;
                ldsm_x2t(vh, sVh + (uint32_t)((vrow*FLD + vcol)*2));
                ldsm_x2t(vl, sVl + (uint32_t)((vrow*FLD + vcol)*2));
                mma16816(oc[nb], pal, vh);
                mma16816(oc[nb], pah, vl);
                mma16816(oc[nb], pah, vh);
            }
        }
    }

    {
        float inv_lo = 1.f / l_lo;
        float inv_hi = 1.f / l_hi;
        size_t base_lo = ((size_t)(b*SEQ + row_lo))*QDIM + h*HD;
        size_t base_hi = ((size_t)(b*SEQ + row_hi))*QDIM + h*HD;
        #pragma unroll
        for (int nb = 0; nb < 16; nb++) {
            int n0 = nb*8 + (lane & 3)*2;
            float f0 = oc[nb][0]*inv_lo, f1 = oc[nb][1]*inv_lo;
            float f2 = oc[nb][2]*inv_hi, f3 = oc[nb][3]*inv_hi;
            bf16 h0, l0, h1, l1, h2, l2, h3, l3;
            bf16_split(f0, h0, l0);
            bf16_split(f1, h1, l1);
            bf16_split(f2, h2, l2);
            bf16_split(f3, h3, l3);
            *(uint32_t*)&g_Ah[base_lo + n0] = pack_bf2(__bfloat162float(h0), __bfloat162float(h1));
            *(uint32_t*)&g_Al[base_lo + n0] = pack_bf2(__bfloat162float(l0), __bfloat162float(l1));
            *(uint32_t*)&g_Ah[base_hi + n0] = pack_bf2(__bfloat162float(h2), __bfloat162float(h3));
            *(uint32_t*)&g_Al[base_hi + n0] = pack_bf2(__bfloat162float(l2), __bfloat162float(l3));
        }
    }
}

// ---------------------------------------------------------------------------
// launch
// ---------------------------------------------------------------------------
extern "C" void kernel_launch(void* const* d_in, const int* in_sizes, int n_in,
                              void* d_out, int out_size)
{
    (void)in_sizes; (void)n_in; (void)out_size;
    const float* hs   = (const float*)d_in[0];
    const float* cosp = (const float*)d_in[1];
    const float* sinp = (const float*)d_in[2];
    const float* Wq   = (const float*)d_in[3];
    const float* bq   = (const float*)d_in[4];
    const float* Wk   = (const float*)d_in[5];
    const float* bk   = (const float*)d_in[6];
    const float* Wv   = (const float*)d_in[7];
    const float* bv   = (const float*)d_in[8];
    const float* Wo   = (const float*)d_in[9];
    float* out = (float*)d_out;

    float *Cqkv;
    bf16 *hsh, *hsl, *Wch, *Wcl, *Woh, *Wol, *Ah, *Al;
    cudaGetSymbolAddress((void**)&Cqkv, g_Cqkv);
    cudaGetSymbolAddress((void**)&hsh, g_hsh);
    cudaGetSymbolAddress((void**)&hsl, g_hsl);
    cudaGetSymbolAddress((void**)&Wch, g_Wch);
    cudaGetSymbolAddress((void**)&Wcl, g_Wcl);
    cudaGetSymbolAddress((void**)&Woh, g_Woh);
    cudaGetSymbolAddress((void**)&Wol, g_Wol);
    cudaGetSymbolAddress((void**)&Ah,  g_Ah);
    cudaGetSymbolAddress((void**)&Al,  g_Al);

    cudaFuncSetAttribute(gemm_v4,
                         cudaFuncAttributeMaxDynamicSharedMemorySize,
                         SMEM3_BYTES);
    cudaFuncSetAttribute(attn_fa2,
                         cudaFuncAttributeMaxDynamicSharedMemorySize,
                         FATTN_SMEM);

    auto split = [&](const float* src, bf16* hi, bf16* lo, size_t n) {
        size_t n4 = n / 4;
        split_bf16<<<(unsigned)((n4 + 255)/256), 256>>>(
            (const float4*)src, (__nv_bfloat162*)hi, (__nv_bfloat162*)lo, n4);
    };
    split(hs, hsh, hsl, (size_t)M_TOK*HIDDEN);
    split(Wq, Wch,                               Wcl,                               (size_t)QDIM*HIDDEN);
    split(Wk, Wch + (size_t)QDIM*HIDDEN,         Wcl + (size_t)QDIM*HIDDEN,         (size_t)KVDIM*HIDDEN);
    split(Wv, Wch + (size_t)(QDIM+KVDIM)*HIDDEN, Wcl + (size_t)(QDIM+KVDIM)*HIDDEN, (size_t)KVDIM*HIDDEN);
    split(Wo, Woh, Wol, (size_t)HIDDEN*QDIM);

    gemm_v4<<<dim3(NDIMC/BN3, M_TOK/BM3), 256, SMEM3_BYTES>>>(
        hsh, hsl, Wch, Wcl, Cqkv, M_TOK, NDIMC, HIDDEN);
    pack_rope<<<M_TOK, 256>>>(Cqkv, bq, bk, bv, cosp, sinp);
    attn_fa2<<<dim3(NQT, NH, BATCH), 256, FATTN_SMEM>>>();
    gemm_v4<<<dim3(QDIM/BN3, M_TOK/BM3), 256, SMEM3_BYTES>>>(
        Ah, Al, Woh, Wol, out, M_TOK, QDIM, HIDDEN);
}

// round 10
// speedup vs baseline: 5.3574x; 1.0071x over previous
#include <cuda_runtime.h>
#include <cuda_bf16.h>
#include <mma.h>
#include <math.h>
#include <cstdint>
#include <cstddef>

#define HIDDEN 3584
#define NH 28
#define NKV 4
#define HD 128
#define NREP 7
#define BATCH 2
#define SEQ 2048
#define M_TOK (BATCH*SEQ)   // 4096
#define QDIM (NH*HD)        // 3584
#define KVDIM (NKV*HD)      // 512
#define NDIMC (QDIM + 2*KVDIM)   // 4608

typedef __nv_bfloat16 bf16;

// ---------------------------------------------------------------------------
// Scratch
// ---------------------------------------------------------------------------
__device__ float g_Cqkv[(size_t)M_TOK*NDIMC];

__device__ __align__(128) bf16 g_hsh[(size_t)M_TOK*HIDDEN];
__device__ __align__(128) bf16 g_hsl[(size_t)M_TOK*HIDDEN];
__device__ __align__(128) bf16 g_Wch[(size_t)NDIMC*HIDDEN];
__device__ __align__(128) bf16 g_Wcl[(size_t)NDIMC*HIDDEN];
__device__ __align__(128) bf16 g_Woh[(size_t)HIDDEN*QDIM];
__device__ __align__(128) bf16 g_Wol[(size_t)HIDDEN*QDIM];

__device__ __align__(128) bf16 g_Qh[(size_t)M_TOK*QDIM];   // [B][NH][S][D]
__device__ __align__(128) bf16 g_Ql[(size_t)M_TOK*QDIM];
__device__ __align__(128) bf16 g_Kh[(size_t)M_TOK*KVDIM];  // [B][NKV][S][D]
__device__ __align__(128) bf16 g_Kl[(size_t)M_TOK*KVDIM];
__device__ __align__(128) bf16 g_Vh[(size_t)M_TOK*KVDIM];
__device__ __align__(128) bf16 g_Vl[(size_t)M_TOK*KVDIM];
__device__ __align__(128) bf16 g_Ah[(size_t)M_TOK*QDIM];
__device__ __align__(128) bf16 g_Al[(size_t)M_TOK*QDIM];

// ---------------------------------------------------------------------------
// helpers
// ---------------------------------------------------------------------------
__device__ __forceinline__ void bf16_split(float x, bf16& hi, bf16& lo) {
    hi = __float2bfloat16(x);
    lo = __float2bfloat16(x - __bfloat162float(hi));
}
__device__ __forceinline__ uint32_t smem_u32(const void* p) {
    return (uint32_t)__cvta_generic_to_shared(p);
}
__device__ __forceinline__ void cp_async16_sm(uint32_t s, const void* g) {
    asm volatile("cp.async.cg.shared.global [%0], [%1], 16;\n"
                 :: "r"(s), "l"(g));
}
__device__ __forceinline__ void ldsm_x4(uint32_t r[4], uint32_t addr) {
    asm volatile("ldmatrix.sync.aligned.m8n8.x4.shared.b16 {%0,%1,%2,%3}, [%4];"
        : "=r"(r[0]), "=r"(r[1]), "=r"(r[2]), "=r"(r[3]) : "r"(addr));
}
__device__ __forceinline__ void ldsm_x4t(uint32_t r[4], uint32_t addr) {
    asm volatile("ldmatrix.sync.aligned.m8n8.x4.trans.shared.b16 {%0,%1,%2,%3}, [%4];"
        : "=r"(r[0]), "=r"(r[1]), "=r"(r[2]), "=r"(r[3]) : "r"(addr));
}
__device__ __forceinline__ void mma16816(float d[4], const uint32_t a[4],
                                         const uint32_t b[2]) {
    asm volatile(
        "mma.sync.aligned.m16n8k16.row.col.f32.bf16.bf16.f32 "
        "{%0,%1,%2,%3}, {%4,%5,%6,%7}, {%8,%9}, {%0,%1,%2,%3};"
        : "+f"(d[0]), "+f"(d[1]), "+f"(d[2]), "+f"(d[3])
        : "r"(a[0]), "r"(a[1]), "r"(a[2]), "r"(a[3]), "r"(b[0]), "r"(b[1]));
}
__device__ __forceinline__ uint32_t pack_bf2(float lo, float hi) {
    __nv_bfloat162 v(__float2bfloat16(lo), __float2bfloat16(hi));
    return *(uint32_t*)&v;
}

// elementwise split fp32 -> bf16 hi/lo
__global__ void __launch_bounds__(256) split_bf16(
    const float4* __restrict__ src, __nv_bfloat162* __restrict__ hi,
    __nv_bfloat162* __restrict__ lo, size_t n4)
{
    size_t i = (size_t)blockIdx.x*blockDim.x + threadIdx.x;
    if (i >= n4) return;
    float4 v = src[i];
    bf16 hx, lx, hy, ly, hz, lz, hw, lw;
    bf16_split(v.x, hx, lx);
    bf16_split(v.y, hy, ly);
    bf16_split(v.z, hz, lz);
    bf16_split(v.w, hw, lw);
    hi[2*i]   = __nv_bfloat162(hx, hy);
    hi[2*i+1] = __nv_bfloat162(hz, hw);
    lo[2*i]   = __nv_bfloat162(lx, ly);
    lo[2*i+1] = __nv_bfloat162(lz, lw);
}

// ---------------------------------------------------------------------------
// 3xBF16 GEMM v5: ldsm_x4 pair-loaded B fragments, software pipelined.
// BM=256 BN=128 BK=64, 2-stage cp.async, 8 warps, warp tile 64x64.
// ---------------------------------------------------------------------------
#define BM3 256
#define BN3 128
#define BK3 64
#define LDT3 72
#define OFF3_AH 0
#define OFF3_AL (BM3*LDT3)
#define OFF3_BH (2*BM3*LDT3)
#define OFF3_BL (2*BM3*LDT3 + BN3*LDT3)
#define STAGE3_HALFS (2*BM3*LDT3 + 2*BN3*LDT3)   // 55296
#define SMEM3_BYTES (2*STAGE3_HALFS*2)           // 221184

__global__ void __launch_bounds__(256,1) gemm_v5(
    const bf16* __restrict__ Ah, const bf16* __restrict__ Al,
    const bf16* __restrict__ Wh, const bf16* __restrict__ Wl,
    float* __restrict__ C, int M, int N, int K)
{
    extern __shared__ __align__(16) bf16 sm[];
    const uint32_t smb = smem_u32(sm);
    const int tid  = threadIdx.x;
    const int warp = tid >> 5;
    const int lane = tid & 31;
    const int wr   = warp >> 1;        // 0..3 : 64-row band
    const int wc   = warp & 1;         // 0..1 : 64-col band
    const int bm   = blockIdx.y * BM3;
    const int bn   = blockIdx.x * BN3;

    float acc[4][8][4];
    #pragma unroll
    for (int mi = 0; mi < 4; mi++)
        #pragma unroll
        for (int nb = 0; nb < 8; nb++)
            #pragma unroll
            for (int c = 0; c < 4; c++) acc[mi][nb][c] = 0.f;

    auto load_chunk = [&](int chunk, int slot) {
        const int k0 = chunk * BK3;
        const uint32_t base = smb + (uint32_t)(slot*STAGE3_HALFS*2);
        #pragma unroll
        for (int it = 0; it < 24; it++) {
            int c = tid + it*256;
            const bf16* g;
            uint32_t soff;
            if (c < 4096) {
                int t = c >> 11, idx = c & 2047;
                int row = idx >> 3, c16 = idx & 7;
                g = (t ? Al : Ah) + (size_t)(bm+row)*K + k0 + c16*8;
                soff = (uint32_t)(((t ? OFF3_AL : OFF3_AH) + row*LDT3 + c16*8) * 2);
            } else {
                int d = c - 4096;
                int t = d >> 10, idx = d & 1023;
                int row = idx >> 3, c16 = idx & 7;
                g = (t ? Wl : Wh) + (size_t)(bn+row)*K + k0 + c16*8;
                soff = (uint32_t)(((t ? OFF3_BL : OFF3_BH) + row*LDT3 + c16*8) * 2);
            }
            cp_async16_sm(base + soff, g);
        }
        asm volatile("cp.async.commit_group;" ::: "memory");
    };

    // A ldsm.x4 addressing: m0=(r,k0) m1=(r+8,k0) m2=(r,k8) m3=(r+8,k8)
    const int arow  = wr*64 + (lane & 7) + ((lane >> 3) & 1)*8;   // + mi*16
    const int acol8 = ((lane >> 4) & 1)*8;
    // B ldsm.x4 pair addressing: m0=(nb,k0) m1=(nb,k8) m2=(nb+1,k0) m3=(nb+1,k8)
    const int brow  = wc*64 + (lane & 7) + ((lane >> 4) & 1)*8;   // + np*16
    const int bcol8 = ((lane >> 3) & 1)*8;

    const int T = K / BK3;
    load_chunk(0, 0);

    for (int i = 0; i < T; i++) {
        const int slot = i & 1;
        asm volatile("cp.async.wait_group 0;" ::: "memory");
        __syncthreads();
        if (i + 1 < T) load_chunk(i + 1, slot ^ 1);

        const uint32_t st = smb + (uint32_t)(slot*STAGE3_HALFS*2);
        const uint32_t sAh = st + OFF3_AH*2;
        const uint32_t sAl = st + OFF3_AL*2;
        const uint32_t sBh = st + OFF3_BH*2;
        const uint32_t sBl = st + OFF3_BL*2;

        #pragma unroll
        for (int ks = 0; ks < 4; ks++) {
            const int kofs = ks*16;
            uint32_t ah[4][4], al[4][4];
            #pragma unroll
            for (int mi = 0; mi < 4; mi++) {
                uint32_t ao = (uint32_t)(((arow + mi*16)*LDT3 + kofs + acol8)*2);
                ldsm_x4(ah[mi], sAh + ao);
                ldsm_x4(al[mi], sAl + ao);
            }
            // double-buffered B n8-pairs via ldsm.x4
            uint32_t bh[2][4], bl[2][4];
            {
                uint32_t bo = (uint32_t)((brow*LDT3 + kofs + bcol8)*2);
                ldsm_x4(bh[0], sBh + bo);
                ldsm_x4(bl[0], sBl + bo);
            }
            #pragma unroll
            for (int np = 0; np < 4; np++) {
                const int cur = np & 1;
                if (np < 3) {
                    uint32_t bo = (uint32_t)(((brow + (np+1)*16)*LDT3 + kofs + bcol8)*2);
                    ldsm_x4(bh[cur ^ 1], sBh + bo);
                    ldsm_x4(bl[cur ^ 1], sBl + bo);
                }
                #pragma unroll
                for (int mi = 0; mi < 4; mi++) {
                    mma16816(acc[mi][2*np],   al[mi], &bh[cur][0]);
                    mma16816(acc[mi][2*np],   ah[mi], &bl[cur][0]);
                    mma16816(acc[mi][2*np],   ah[mi], &bh[cur][0]);
                    mma16816(acc[mi][2*np+1], al[mi], &bh[cur][2]);
                    mma16816(acc[mi][2*np+1], ah[mi], &bl[cur][2]);
                    mma16816(acc[mi][2*np+1], ah[mi], &bh[cur][2]);
                }
            }
        }
    }

    {
        const int r0 = bm + wr*64 + (lane >> 2);
        const int c0 = bn + wc*64 + (lane & 3)*2;
        #pragma unroll
        for (int mi = 0; mi < 4; mi++)
            #pragma unroll
            for (int nb = 0; nb < 8; nb++) {
                float* p0 = &C[(size_t)(r0 + mi*16)*N + c0 + nb*8];
                float* p1 = &C[(size_t)(r0 + mi*16 + 8)*N + c0 + nb*8];
                *(float2*)p0 = make_float2(acc[mi][nb][0], acc[mi][nb][1]);
                *(float2*)p1 = make_float2(acc[mi][nb][2], acc[mi][nb][3]);
            }
    }
}

// ---------------------------------------------------------------------------
// bias + RoPE + transpose; folds (1/sqrt(128))*log2(e) into Q.
// ---------------------------------------------------------------------------
__global__ void __launch_bounds__(256) pack_rope(
    const float* __restrict__ Cqkv,
    const float* __restrict__ bq, const float* __restrict__ bk,
    const float* __restrict__ bv,
    const float* __restrict__ cosp, const float* __restrict__ sinp)
{
    const int token = blockIdx.x;
    const int b = token / SEQ, s = token % SEQ;
    __shared__ float cs[HD], sn[HD];
    if (threadIdx.x < HD) {
        cs[threadIdx.x] = cosp[(size_t)token*HD + threadIdx.x];
        sn[threadIdx.x] = sinp[(size_t)token*HD + threadIdx.x];
    }
    __syncthreads();
    const float scaling = 0.08838834764831845f * 1.4426950408889634f;
    const float* Crow = Cqkv + (size_t)token*NDIMC;

    for (int i = threadIdx.x; i < NH*64; i += blockDim.x) {
        int h = i >> 6, d = i & 63;
        float x1 = Crow[h*HD + d]      + bq[h*HD + d];
        float x2 = Crow[h*HD + d + 64] + bq[h*HD + d + 64];
        float o1 = (x1*cs[d]      - x2*sn[d])      * scaling;
        float o2 = (x2*cs[d + 64] + x1*sn[d + 64]) * scaling;
        size_t ob = ((size_t)(b*NH + h)*SEQ + s)*HD;
        bf16 h1, l1, h2, l2;
        bf16_split(o1, h1, l1);
        bf16_split(o2, h2, l2);
        g_Qh[ob + d] = h1;      g_Ql[ob + d] = l1;
        g_Qh[ob + d + 64] = h2; g_Ql[ob + d + 64] = l2;
    }
    for (int i = threadIdx.x; i < NKV*64; i += blockDim.x) {
        int h = i >> 6, d = i & 63;
        float x1 = Crow[QDIM + h*HD + d]      + bk[h*HD + d];
        float x2 = Crow[QDIM + h*HD + d + 64] + bk[h*HD + d + 64];
        float o1 = x1*cs[d]      - x2*sn[d];
        float o2 = x2*cs[d + 64] + x1*sn[d + 64];
        size_t ob = ((size_t)(b*NKV + h)*SEQ + s)*HD;
        bf16 h1, l1, h2, l2;
        bf16_split(o1, h1, l1);
        bf16_split(o2, h2, l2);
        g_Kh[ob + d] = h1;      g_Kl[ob + d] = l1;
        g_Kh[ob + d + 64] = h2; g_Kl[ob + d + 64] = l2;
    }
    for (int i = threadIdx.x; i < KVDIM; i += blockDim.x) {
        int h = i >> 7, d = i & 127;
        float v = Crow[QDIM + KVDIM + i] + bv[i];
        size_t ob = ((size_t)(b*NKV + h)*SEQ + s)*HD + d;
        bf16 hv, lv;
        bf16_split(v, hv, lv);
        g_Vh[ob] = hv; g_Vl[ob] = lv;
    }
}

// ---------------------------------------------------------------------------
// FlashAttention-2 causal GQA attention, ldsm.x4 pair loads.
// ---------------------------------------------------------------------------
#define FBQ 128
#define FBKV 64
#define FLD 136
#define FQT_HALFS (128*FLD)
#define FKV_HALFS (64*FLD)
#define FSTAGE_HALFS (4*FKV_HALFS)
#define FQ_BYTES (2*FQT_HALFS*2)
#define FSTAGE_BYTES (FSTAGE_HALFS*2)
#define FKV_BYTES (FKV_HALFS*2)
#define FATTN_SMEM (FQ_BYTES + 2*FSTAGE_BYTES)
#define NQT (SEQ/FBQ)

__global__ void __launch_bounds__(256) attn_fa2()
{
    extern __shared__ __align__(16) char smraw[];
    const uint32_t smb = smem_u32(smraw);
    const uint32_t sQh = smb;
    const uint32_t sQl = smb + FQT_HALFS*2;

    const int qt  = (NQT - 1) - blockIdx.x;   // heavy tiles first
    const int h   = blockIdx.y;
    const int b   = blockIdx.z;
    const int kvh = h / NREP;
    const int q0  = qt * FBQ;
    const int tid = threadIdx.x;
    const int warp = tid >> 5;
    const int lane = tid & 31;
    const int R = warp * 16;

    const bf16* Qgh = g_Qh + (size_t)(b*NH  + h  )*SEQ*HD;
    const bf16* Qgl = g_Ql + (size_t)(b*NH  + h  )*SEQ*HD;
    const bf16* Kgh = g_Kh + (size_t)(b*NKV + kvh)*SEQ*HD;
    const bf16* Kgl = g_Kl + (size_t)(b*NKV + kvh)*SEQ*HD;
    const bf16* Vgh = g_Vh + (size_t)(b*NKV + kvh)*SEQ*HD;
    const bf16* Vgl = g_Vl + (size_t)(b*NKV + kvh)*SEQ*HD;

    {
        bf16* qsm = (bf16*)smraw;
        #pragma unroll
        for (int it = 0; it < 16; it++) {
            int c = tid + it*256;
            int t = c >> 11, idx = c & 2047;
            int row = idx >> 4, c16 = idx & 15;
            const bf16* src = (t ? Qgl : Qgh) + (size_t)(q0+row)*HD + c16*8;
            *(uint4*)(qsm + t*FQT_HALFS + row*FLD + c16*8) = *(const uint4*)src;
        }
    }

    auto load_kv = [&](int j, int s) {
        const uint32_t base = smb + FQ_BYTES + (uint32_t)(s*FSTAGE_BYTES);
        #pragma unroll
        for (int it = 0; it < 16; it++) {
            int c = tid + it*256;
            int t = c >> 10, idx = c & 1023;
            int row = idx >> 4, c16 = idx & 15;
            const bf16* src;
            if      (t == 0) src = Kgh;
            else if (t == 1) src = Kgl;
            else if (t == 2) src = Vgh;
            else             src = Vgl;
            cp_async16_sm(base + (uint32_t)((t*FKV_HALFS + row*FLD + c16*8)*2),
                          src + (size_t)(j*FBKV+row)*HD + c16*8);
        }
        asm volatile("cp.async.commit_group;" ::: "memory");
    };

    const int nt = 2*qt + 2;
    load_kv(0, 0);
    __syncthreads();

    float oc[16][4];
    #pragma unroll
    for (int i = 0; i < 16; i++)
        #pragma unroll
        for (int c = 0; c < 4; c++) oc[i][c] = 0.f;
    float m_lo = -INFINITY, m_hi = -INFINITY;
    float l_lo = 0.f, l_hi = 0.f;

    const int row_lo = q0 + R + (lane >> 2);
    const int row_hi = row_lo + 8;

    // pair-load addressing
    const int qrow  = R + (lane & 7) + ((lane >> 3) & 1)*8;
    const int qcol8 = ((lane >> 4) & 1)*8;
    const int krow  = (lane & 7) + ((lane >> 4) & 1)*8;     // + np*16
    const int kcol8 = ((lane >> 3) & 1)*8;
    const int vrow  = (lane & 7) + ((lane >> 3) & 1)*8;     // + ks2*16
    const int vcol8 = ((lane >> 4) & 1)*8;                  // + np*16

    for (int j = 0; j < nt; j++) {
        const int s = j & 1;
        asm volatile("cp.async.wait_group 0;" ::: "memory");
        __syncthreads();
        if (j + 1 < nt) load_kv(j + 1, s ^ 1);

        if (j*FBKV > q0 + R + 15) continue;

        const uint32_t stg = smb + FQ_BYTES + (uint32_t)(s*FSTAGE_BYTES);
        const uint32_t sKh = stg;
        const uint32_t sKl = stg + FKV_BYTES;
        const uint32_t sVh = stg + 2*FKV_BYTES;
        const uint32_t sVl = stg + 3*FKV_BYTES;

        float sc[8][4];
        #pragma unroll
        for (int nb = 0; nb < 8; nb++)
            #pragma unroll
            for (int c = 0; c < 4; c++) sc[nb][c] = 0.f;

        #pragma unroll
        for (int ks = 0; ks < 8; ks++) {
            uint32_t qh[4], ql[4];
            uint32_t qo = (uint32_t)((qrow*FLD + ks*16 + qcol8)*2);
            ldsm_x4(qh, sQh + qo);
            ldsm_x4(ql, sQl + qo);
            #pragma unroll
            for (int np = 0; np < 4; np++) {
                uint32_t kh[4], kl[4];
                uint32_t ko = (uint32_t)(((np*16 + krow)*FLD + ks*16 + kcol8)*2);
                ldsm_x4(kh, sKh + ko);
                ldsm_x4(kl, sKl + ko);
                mma16816(sc[2*np],   ql, &kh[0]);
                mma16816(sc[2*np],   qh, &kl[0]);
                mma16816(sc[2*np],   qh, &kh[0]);
                mma16816(sc[2*np+1], ql, &kh[2]);
                mma16816(sc[2*np+1], qh, &kl[2]);
                mma16816(sc[2*np+1], qh, &kh[2]);
            }
        }

        const bool masked = (j*FBKV + 63 > q0 + R);
        const int cb = j*FBKV + (lane & 3)*2;
        float tmlo = -INFINITY, tmhi = -INFINITY;
        if (!masked) {
            #pragma unroll
            for (int nb = 0; nb < 8; nb++) {
                tmlo = fmaxf(tmlo, fmaxf(sc[nb][0], sc[nb][1]));
                tmhi = fmaxf(tmhi, fmaxf(sc[nb][2], sc[nb][3]));
            }
        } else {
            #pragma unroll
            for (int nb = 0; nb < 8; nb++) {
                int c0 = cb + nb*8, c1 = c0 + 1;
                if (c0 <= row_lo) tmlo = fmaxf(tmlo, sc[nb][0]);
                if (c1 <= row_lo) tmlo = fmaxf(tmlo, sc[nb][1]);
                if (c0 <= row_hi) tmhi = fmaxf(tmhi, sc[nb][2]);
                if (c1 <= row_hi) tmhi = fmaxf(tmhi, sc[nb][3]);
            }
        }
        tmlo = fmaxf(tmlo, __shfl_xor_sync(0xffffffffu, tmlo, 1));
        tmlo = fmaxf(tmlo, __shfl_xor_sync(0xffffffffu, tmlo, 2));
        tmhi = fmaxf(tmhi, __shfl_xor_sync(0xffffffffu, tmhi, 1));
        tmhi = fmaxf(tmhi, __shfl_xor_sync(0xffffffffu, tmhi, 2));

        float mn_lo = fmaxf(m_lo, tmlo);
        float mn_hi = fmaxf(m_hi, tmhi);
        float alpha_lo = exp2f(m_lo - mn_lo);
        float alpha_hi = exp2f(m_hi - mn_hi);
        m_lo = mn_lo; m_hi = mn_hi;
        #pragma unroll
        for (int nb = 0; nb < 16; nb++) {
            oc[nb][0] *= alpha_lo; oc[nb][1] *= alpha_lo;
            oc[nb][2] *= alpha_hi; oc[nb][3] *= alpha_hi;
        }

        float slo = 0.f, shi = 0.f;
        #pragma unroll
        for (int nb = 0; nb < 8; nb++) {
            float p0 = exp2f(sc[nb][0] - mn_lo);
            float p1 = exp2f(sc[nb][1] - mn_lo);
            float p2 = exp2f(sc[nb][2] - mn_hi);
            float p3 = exp2f(sc[nb][3] - mn_hi);
            if (masked) {
                int c0 = cb + nb*8, c1 = c0 + 1;
                if (c0 > row_lo) p0 = 0.f;
                if (c1 > row_lo) p1 = 0.f;
                if (c0 > row_hi) p2 = 0.f;
                if (c1 > row_hi) p3 = 0.f;
            }
            sc[nb][0] = p0; sc[nb][1] = p1; sc[nb][2] = p2; sc[nb][3] = p3;
            slo += p0 + p1; shi += p2 + p3;
        }
        slo += __shfl_xor_sync(0xffffffffu, slo, 1);
        slo += __shfl_xor_sync(0xffffffffu, slo, 2);
        shi += __shfl_xor_sync(0xffffffffu, shi, 1);
        shi += __shfl_xor_sync(0xffffffffu, shi, 2);
        l_lo = l_lo * alpha_lo + slo;
        l_hi = l_hi * alpha_hi + shi;

        #pragma unroll
        for (int ks2 = 0; ks2 < 4; ks2++) {
            uint32_t pah[4], pal[4];
            #pragma unroll
            for (int half = 0; half < 2; half++) {
                const float* f = sc[2*ks2 + half];
                bf16 h0, l0, h1, l1, h2, l2, h3, l3;
                bf16_split(f[0], h0, l0);
                bf16_split(f[1], h1, l1);
                bf16_split(f[2], h2, l2);
                bf16_split(f[3], h3, l3);
                pah[half*2 + 0] = pack_bf2(__bfloat162float(h0), __bfloat162float(h1));
                pah[half*2 + 1] = pack_bf2(__bfloat162float(h2), __bfloat162float(h3));
                pal[half*2 + 0] = pack_bf2(__bfloat162float(l0), __bfloat162float(l1));
                pal[half*2 + 1] = pack_bf2(__bfloat162float(l2), __bfloat162float(l3));
            }
            #pragma unroll
            for (int np = 0; np < 8; np++) {
                uint32_t vh[4], vl[4];
                uint32_t vo = (uint32_t)(((ks2*16 + vrow)*FLD + np*16 + vcol8)*2);
                ldsm_x4t(vh, sVh + vo);
                ldsm_x4t(vl, sVl + vo);
                mma16816(oc[2*np],   pal, &vh[0]);
                mma16816(oc[2*np],   pah, &vl[0]);
                mma16816(oc[2*np],   pah, &vh[0]);
                mma16816(oc[2*np+1], pal, &vh[2]);
                mma16816(oc[2*np+1], pah, &vl[2]);
                mma16816(oc[2*np+1], pah, &vh[2]);
            }
        }
    }

    {
        float inv_lo = 1.f / l_lo;
        float inv_hi = 1.f / l_hi;
        size_t base_lo = ((size_t)(b*SEQ + row_lo))*QDIM + h*HD;
        size_t base_hi = ((size_t)(b*SEQ + row_hi))*QDIM + h*HD;
        #pragma unroll
        for (int nb = 0; nb < 16; nb++) {
            int n0 = nb*8 + (lane & 3)*2;
            float f0 = oc[nb][0]*inv_lo, f1 = oc[nb][1]*inv_lo;
            float f2 = oc[nb][2]*inv_hi, f3 = oc[nb][3]*inv_hi;
            bf16 h0, l0, h1, l1, h2, l2, h3, l3;
            bf16_split(f0, h0, l0);
            bf16_split(f1, h1, l1);
            bf16_split(f2, h2, l2);
            bf16_split(f3, h3, l3);
            *(uint32_t*)&g_Ah[base_lo + n0] = pack_bf2(__bfloat162float(h0), __bfloat162float(h1));
            *(uint32_t*)&g_Al[base_lo + n0] = pack_bf2(__bfloat162float(l0), __bfloat162float(l1));
            *(uint32_t*)&g_Ah[base_hi + n0] = pack_bf2(__bfloat162float(h2), __bfloat162float(h3));
            *(uint32_t*)&g_Al[base_hi + n0] = pack_bf2(__bfloat162float(l2), __bfloat162float(l3));
        }
    }
}

// ---------------------------------------------------------------------------
// launch
// ---------------------------------------------------------------------------
extern "C" void kernel_launch(void* const* d_in, const int* in_sizes, int n_in,
                              void* d_out, int out_size)
{
    (void)in_sizes; (void)n_in; (void)out_size;
    const float* hs   = (const float*)d_in[0];
    const float* cosp = (const float*)d_in[1];
    const float* sinp = (const float*)d_in[2];
    const float* Wq   = (const float*)d_in[3];
    const float* bq   = (const float*)d_in[4];
    const float* Wk   = (const float*)d_in[5];
    const float* bk   = (const float*)d_in[6];
    const float* Wv   = (const float*)d_in[7];
    const float* bv   = (const float*)d_in[8];
    const float* Wo   = (const float*)d_in[9];
    float* out = (float*)d_out;

    float *Cqkv;
    bf16 *hsh, *hsl, *Wch, *Wcl, *Woh, *Wol, *Ah, *Al;
    cudaGetSymbolAddress((void**)&Cqkv, g_Cqkv);
    cudaGetSymbolAddress((void**)&hsh, g_hsh);
    cudaGetSymbolAddress((void**)&hsl, g_hsl);
    cudaGetSymbolAddress((void**)&Wch, g_Wch);
    cudaGetSymbolAddress((void**)&Wcl, g_Wcl);
    cudaGetSymbolAddress((void**)&Woh, g_Woh);
    cudaGetSymbolAddress((void**)&Wol, g_Wol);
    cudaGetSymbolAddress((void**)&Ah,  g_Ah);
    cudaGetSymbolAddress((void**)&Al,  g_Al);

    cudaFuncSetAttribute(gemm_v5,
                         cudaFuncAttributeMaxDynamicSharedMemorySize,
                         SMEM3_BYTES);
    cudaFuncSetAttribute(attn_fa2,
                         cudaFuncAttributeMaxDynamicSharedMemorySize,
                         FATTN_SMEM);

    auto split = [&](const float* src, bf16* hi, bf16* lo, size_t n) {
        size_t n4 = n / 4;
        split_bf16<<<(unsigned)((n4 + 255)/256), 256>>>(
            (const float4*)src, (__nv_bfloat162*)hi, (__nv_bfloat162*)lo, n4);
    };
    split(hs, hsh, hsl, (size_t)M_TOK*HIDDEN);
    split(Wq, Wch,                               Wcl,                               (size_t)QDIM*HIDDEN);
    split(Wk, Wch + (size_t)QDIM*HIDDEN,         Wcl + (size_t)QDIM*HIDDEN,         (size_t)KVDIM*HIDDEN);
    split(Wv, Wch + (size_t)(QDIM+KVDIM)*HIDDEN, Wcl + (size_t)(QDIM+KVDIM)*HIDDEN, (size_t)KVDIM*HIDDEN);
    split(Wo, Woh, Wol, (size_t)HIDDEN*QDIM);

    gemm_v5<<<dim3(NDIMC/BN3, M_TOK/BM3), 256, SMEM3_BYTES>>>(
        hsh, hsl, Wch, Wcl, Cqkv, M_TOK, NDIMC, HIDDEN);
    pack_rope<<<M_TOK, 256>>>(Cqkv, bq, bk, bv, cosp, sinp);
    attn_fa2<<<dim3(NQT, NH, BATCH), 256, FATTN_SMEM>>>();
    gemm_v5<<<dim3(QDIM/BN3, M_TOK/BM3), 256, SMEM3_BYTES>>>(
        Ah, Al, Woh, Wol, out, M_TOK, QDIM, HIDDEN);
}